// round 2
// baseline (speedup 1.0000x reference)
#include <cuda_runtime.h>
#include <math.h>

// Problem constants
#define B_    4096
#define D_    2048
#define H_    2048
#define NB_   4
#define BIN_  512
#define BOUT_ 512
#define EPS_  1e-5f

// Scratch (device globals: allocation-free, graph-capture safe)
__device__ float g_xconv[(size_t)B_ * D_];                 // SiLU(conv(LN(x)))
__device__ float g_pre[4ull * B_ * H_];                    // pre-activations z,i,f,o

// ---------------------------------------------------------------------------
// Kernel 1: LayerNorm over feature dim, causal conv1d (k=3), SiLU
// One CTA per batch row. 256 threads, 8 elems/thread.
// ---------------------------------------------------------------------------
__global__ __launch_bounds__(256) void ln_conv_kernel(
    const float* __restrict__ x,
    const float* __restrict__ ln_g,
    const float* __restrict__ ln_b,
    const float* __restrict__ conv_w,
    const float* __restrict__ conv_b,
    float* __restrict__ xconv)
{
    __shared__ float xn[D_];
    __shared__ float red[256];

    const int row = blockIdx.x;
    const int tid = threadIdx.x;
    const float* xr = x + (size_t)row * D_;

    float v[8];
    float s = 0.f, ss = 0.f;
#pragma unroll
    for (int i = 0; i < 8; ++i) {
        float t = xr[tid + i * 256];
        v[i] = t;
        s += t;
        ss += t * t;
    }

    // reduce sum
    red[tid] = s;
    __syncthreads();
    for (int off = 128; off > 0; off >>= 1) {
        if (tid < off) red[tid] += red[tid + off];
        __syncthreads();
    }
    const float mean = red[0] * (1.0f / D_);
    __syncthreads();

    // reduce sum of squares
    red[tid] = ss;
    __syncthreads();
    for (int off = 128; off > 0; off >>= 1) {
        if (tid < off) red[tid] += red[tid + off];
        __syncthreads();
    }
    const float var = red[0] * (1.0f / D_) - mean * mean;
    const float rstd = rsqrtf(var + EPS_);
    __syncthreads();

    // normalize into smem (needed with neighbors for conv)
#pragma unroll
    for (int i = 0; i < 8; ++i) {
        int d = tid + i * 256;
        xn[d] = (v[i] - mean) * rstd * ln_g[d] + ln_b[d];
    }
    __syncthreads();

    const float w0 = conv_w[0], w1 = conv_w[1], w2 = conv_w[2], cb = conv_b[0];
    float* xo = xconv + (size_t)row * D_;
#pragma unroll
    for (int i = 0; i < 8; ++i) {
        int d = tid + i * 256;
        float a0 = (d >= 2) ? xn[d - 2] : 0.f;
        float a1 = (d >= 1) ? xn[d - 1] : 0.f;
        float xc = w0 * a0 + w1 * a1 + w2 * xn[d] + cb;
        // SiLU
        float sg = 1.f / (1.f + expf(-xc));
        xo[d] = xc * sg;
    }
}

// ---------------------------------------------------------------------------
// Kernel 2: block-diagonal GEMM for one gate.
// pre[b, nblk*512 + j] = sum_k A1[b, nblk*512+k]*W[nblk,k,j]
//                      + sum_k A2[b, nblk*512+k]*R[nblk,k,j]
// Classic SGEMM: 128x128 tile, BK=8, 256 threads, 8x8 microtile.
// grid: (BOUT_/128, B_/128, NB_)
// ---------------------------------------------------------------------------
#define BM 128
#define BN 128
#define BK 8

__global__ __launch_bounds__(256) void gemm_gate_kernel(
    const float* __restrict__ A1,   // [B_, D_]  (x or xconv)
    const float* __restrict__ A2,   // [B_, H_]  (h_prev)
    const float* __restrict__ Wg,   // [NB_, BIN_, BOUT_]
    const float* __restrict__ Rg,   // [NB_, BOUT_, BOUT_]
    float* __restrict__ Cout)       // [B_, H_]  pre-activations
{
    const int nblk = blockIdx.z;
    const int row0 = blockIdx.y * BM;
    const int col0 = blockIdx.x * BN;

    __shared__ float As[BK][BM];
    __shared__ float Bs[BK][BN];

    const int tid = threadIdx.x;
    const int tr = tid >> 4;       // 0..15
    const int tc = tid & 15;       // 0..15

    // load indices
    const int lar = tid >> 1;           // 0..127 A row
    const int lak = (tid & 1) << 2;     // 0 or 4 (k quad)
    const int lbk = tid >> 5;           // 0..7 B k-row
    const int lbj = (tid & 31) << 2;    // 0..124 B col quad

    float acc[8][8];
#pragma unroll
    for (int i = 0; i < 8; ++i)
#pragma unroll
        for (int j = 0; j < 8; ++j) acc[i][j] = 0.f;

#pragma unroll 1
    for (int phase = 0; phase < 2; ++phase) {
        const float* A = (phase == 0 ? A1 : A2) + (size_t)row0 * D_ + nblk * BIN_;
        const float* Bm = (phase == 0 ? Wg : Rg) + (size_t)nblk * BIN_ * BOUT_ + col0;

#pragma unroll 1
        for (int k0 = 0; k0 < BIN_; k0 += BK) {
            float4 av = *(const float4*)(A + (size_t)lar * D_ + k0 + lak);
            float4 bv = *(const float4*)(Bm + (size_t)(k0 + lbk) * BOUT_ + lbj);
            __syncthreads();  // previous iteration's reads done
            As[lak + 0][lar] = av.x;
            As[lak + 1][lar] = av.y;
            As[lak + 2][lar] = av.z;
            As[lak + 3][lar] = av.w;
            *(float4*)&Bs[lbk][lbj] = bv;
            __syncthreads();

#pragma unroll
            for (int kk = 0; kk < BK; ++kk) {
                float a[8], b[8];
                *(float4*)&a[0] = *(const float4*)&As[kk][tr * 4];
                *(float4*)&a[4] = *(const float4*)&As[kk][64 + tr * 4];
                *(float4*)&b[0] = *(const float4*)&Bs[kk][tc * 4];
                *(float4*)&b[4] = *(const float4*)&Bs[kk][64 + tc * 4];
#pragma unroll
                for (int i = 0; i < 8; ++i)
#pragma unroll
                    for (int j = 0; j < 8; ++j)
                        acc[i][j] += a[i] * b[j];
            }
        }
    }

    // write pre-activations (biases added in gate kernel)
#pragma unroll
    for (int i = 0; i < 8; ++i) {
        int r = row0 + ((i < 4) ? (tr * 4 + i) : (64 + tr * 4 + (i - 4)));
        float* crow = Cout + (size_t)r * H_ + nblk * BOUT_ + col0;
        *(float4*)(crow + tc * 4) =
            make_float4(acc[i][0], acc[i][1], acc[i][2], acc[i][3]);
        *(float4*)(crow + 64 + tc * 4) =
            make_float4(acc[i][4], acc[i][5], acc[i][6], acc[i][7]);
    }
}

// ---------------------------------------------------------------------------
// Kernel 3: elementwise gates. Adds biases, applies activations,
// writes h_t to out[0 : B*H] and c_t to out[B*H : 2*B*H].
// ---------------------------------------------------------------------------
__global__ __launch_bounds__(256) void gates_kernel(
    const float* __restrict__ c_prev,
    const float* __restrict__ bz, const float* __restrict__ bi,
    const float* __restrict__ bf, const float* __restrict__ bo,
    const float* __restrict__ rbz, const float* __restrict__ rbi,
    const float* __restrict__ rbf, const float* __restrict__ rbo,
    float* __restrict__ out_h, float* __restrict__ out_c)
{
    size_t idx = (size_t)blockIdx.x * blockDim.x + threadIdx.x;
    if (idx >= (size_t)B_ * H_) return;
    int j = (int)(idx & (H_ - 1));   // bias vectors are [NB_*BOUT_] = [H_] flat

    const size_t n = (size_t)B_ * H_;
    float pz = g_pre[0 * n + idx] + bz[j] + rbz[j];
    float pi = g_pre[1 * n + idx] + bi[j] + rbi[j];
    float pf = g_pre[2 * n + idx] + bf[j] + rbf[j];
    float po = g_pre[3 * n + idx] + bo[j] + rbo[j];

    float z = tanhf(pz);
    float ig = 1.f / (1.f + expf(-pi));
    float fg = 1.f / (1.f + expf(-pf));
    float og = 1.f / (1.f + expf(-po));

    float c = fg * c_prev[idx] + ig * z;
    float h = og * tanhf(c);

    out_h[idx] = h;
    out_c[idx] = c;
}

// ---------------------------------------------------------------------------
// Launch
// ---------------------------------------------------------------------------
extern "C" void kernel_launch(void* const* d_in, const int* in_sizes, int n_in,
                              void* d_out, int out_size)
{
    const float* x      = (const float*)d_in[0];
    const float* h_prev = (const float*)d_in[1];
    const float* c_prev = (const float*)d_in[2];
    const float* ln_g   = (const float*)d_in[3];
    const float* ln_b   = (const float*)d_in[4];
    const float* conv_w = (const float*)d_in[5];
    const float* conv_b = (const float*)d_in[6];
    const float* Wz = (const float*)d_in[7],  *bz  = (const float*)d_in[8];
    const float* Wi = (const float*)d_in[9],  *bi  = (const float*)d_in[10];
    const float* Wf = (const float*)d_in[11], *bf  = (const float*)d_in[12];
    const float* Wo = (const float*)d_in[13], *bo  = (const float*)d_in[14];
    const float* Rz = (const float*)d_in[15], *rbz = (const float*)d_in[16];
    const float* Ri = (const float*)d_in[17], *rbi = (const float*)d_in[18];
    const float* Rf = (const float*)d_in[19], *rbf = (const float*)d_in[20];
    const float* Ro = (const float*)d_in[21], *rbo = (const float*)d_in[22];

    float* out = (float*)d_out;

    void* p;
    cudaGetSymbolAddress(&p, g_xconv);
    float* xconv = (float*)p;
    cudaGetSymbolAddress(&p, g_pre);
    float* pre = (float*)p;
    const size_t nelem = (size_t)B_ * H_;

    // 1) LN + conv + SiLU
    ln_conv_kernel<<<B_, 256>>>(x, ln_g, ln_b, conv_w, conv_b, xconv);

    // 2) 4 gate GEMMs (each fuses W-part and R-part over K)
    dim3 grid(BOUT_ / BN, B_ / BM, NB_);
    gemm_gate_kernel<<<grid, 256>>>(x,     h_prev, Wz, Rz, pre + 0 * nelem);
    gemm_gate_kernel<<<grid, 256>>>(xconv, h_prev, Wi, Ri, pre + 1 * nelem);
    gemm_gate_kernel<<<grid, 256>>>(xconv, h_prev, Wf, Rf, pre + 2 * nelem);
    gemm_gate_kernel<<<grid, 256>>>(x,     h_prev, Wo, Ro, pre + 3 * nelem);

    // 3) gates + state update; output = [h_t | c_t]
    gates_kernel<<<(int)((nelem + 255) / 256), 256>>>(
        c_prev, bz, bi, bf, bo, rbz, rbi, rbf, rbo,
        out, out + nelem);
}

// round 5
// speedup vs baseline: 2.4055x; 2.4055x over previous
#include <cuda_runtime.h>
#include <cuda_bf16.h>
#include <math.h>
#include <stdint.h>

// Problem constants
#define B_    4096
#define D_    2048
#define H_    2048
#define NB_   4
#define BIN_  512
#define BOUT_ 512
#define EPS_  1e-5f

// ---------------------------------------------------------------------------
// Device scratch (allocation-free)
// ---------------------------------------------------------------------------
__device__ __nv_bfloat16 g_xh[(size_t)B_ * D_];
__device__ __nv_bfloat16 g_xl[(size_t)B_ * D_];
__device__ __nv_bfloat16 g_ch[(size_t)B_ * D_];   // SiLU(conv(LN(x))) split
__device__ __nv_bfloat16 g_cl[(size_t)B_ * D_];
__device__ __nv_bfloat16 g_hh[(size_t)B_ * H_];
__device__ __nv_bfloat16 g_hl[(size_t)B_ * H_];
// Transposed + split weights: [tensor 0..7][hi/lo][NB*512*512], row=n, col=k
// tensors: 0..3 = Wz,Wi,Wf,Wo ; 4..7 = Rz,Ri,Rf,Ro
__device__ __nv_bfloat16 g_wt[8][2][(size_t)NB_ * 512 * 512];
__device__ float g_pre[4ull * B_ * H_];

// ---------------------------------------------------------------------------
// PTX helpers (baseline-compute_103-safe: mma.sync / ldmatrix / cp.async only)
// ---------------------------------------------------------------------------
__device__ __forceinline__ uint32_t smem_u32(const void* p) {
    uint32_t a;
    asm("{ .reg .u64 t; cvta.to.shared.u64 t, %1; cvt.u32.u64 %0, t; }"
        : "=r"(a) : "l"(p));
    return a;
}

__device__ __forceinline__ void cp_async16(uint32_t dst, const void* src) {
    asm volatile("cp.async.cg.shared.global [%0], [%1], 16;"
                 :: "r"(dst), "l"(src) : "memory");
}
#define CP_COMMIT() asm volatile("cp.async.commit_group;" ::: "memory")
#define CP_WAIT1()  asm volatile("cp.async.wait_group 1;" ::: "memory")
#define CP_WAIT0()  asm volatile("cp.async.wait_group 0;" ::: "memory")

__device__ __forceinline__ void ldsm4(uint32_t* r, uint32_t addr) {
    asm volatile("ldmatrix.sync.aligned.m8n8.x4.shared.b16 {%0,%1,%2,%3}, [%4];"
                 : "=r"(r[0]), "=r"(r[1]), "=r"(r[2]), "=r"(r[3]) : "r"(addr));
}

__device__ __forceinline__ void mma16816(float* d, const uint32_t* a, const uint32_t* b) {
    asm volatile(
        "mma.sync.aligned.m16n8k16.row.col.f32.bf16.bf16.f32 "
        "{%0,%1,%2,%3}, {%4,%5,%6,%7}, {%8,%9}, {%0,%1,%2,%3};"
        : "+f"(d[0]), "+f"(d[1]), "+f"(d[2]), "+f"(d[3])
        : "r"(a[0]), "r"(a[1]), "r"(a[2]), "r"(a[3]), "r"(b[0]), "r"(b[1]));
}

// swizzled 16B-chunk offset inside a 128row x 64B tile
__device__ __forceinline__ uint32_t swz(int row, int c) {
    return (uint32_t)(row * 64 + ((c ^ ((row >> 1) & 3)) << 4));
}

// ---------------------------------------------------------------------------
// Kernel 1: LayerNorm + causal conv3 + SiLU; writes bf16 hi/lo split directly
// ---------------------------------------------------------------------------
__global__ __launch_bounds__(256) void ln_conv_kernel(
    const float* __restrict__ x,
    const float* __restrict__ ln_g,
    const float* __restrict__ ln_b,
    const float* __restrict__ conv_w,
    const float* __restrict__ conv_b)
{
    __shared__ float xn[D_];
    __shared__ float red[256];

    const int row = blockIdx.x;
    const int tid = threadIdx.x;
    const float* xr = x + (size_t)row * D_;

    float v[8];
    float s = 0.f, ss = 0.f;
#pragma unroll
    for (int i = 0; i < 8; ++i) {
        float t = xr[tid + i * 256];
        v[i] = t; s += t; ss += t * t;
    }
    red[tid] = s; __syncthreads();
    for (int off = 128; off > 0; off >>= 1) {
        if (tid < off) red[tid] += red[tid + off];
        __syncthreads();
    }
    const float mean = red[0] * (1.0f / D_);
    __syncthreads();
    red[tid] = ss; __syncthreads();
    for (int off = 128; off > 0; off >>= 1) {
        if (tid < off) red[tid] += red[tid + off];
        __syncthreads();
    }
    const float var = red[0] * (1.0f / D_) - mean * mean;
    const float rstd = rsqrtf(var + EPS_);
    __syncthreads();

#pragma unroll
    for (int i = 0; i < 8; ++i) {
        int d = tid + i * 256;
        xn[d] = (v[i] - mean) * rstd * ln_g[d] + ln_b[d];
    }
    __syncthreads();

    const float w0 = conv_w[0], w1 = conv_w[1], w2 = conv_w[2], cb = conv_b[0];
    size_t base = (size_t)row * D_;
#pragma unroll
    for (int i = 0; i < 8; ++i) {
        int d = tid + i * 256;
        float a0 = (d >= 2) ? xn[d - 2] : 0.f;
        float a1 = (d >= 1) ? xn[d - 1] : 0.f;
        float xc = w0 * a0 + w1 * a1 + w2 * xn[d] + cb;
        float sg = 1.f / (1.f + expf(-xc));
        float val = xc * sg;
        __nv_bfloat16 hi = __float2bfloat16(val);
        __nv_bfloat16 lo = __float2bfloat16(val - __bfloat162float(hi));
        g_ch[base + d] = hi;
        g_cl[base + d] = lo;
    }
}

// ---------------------------------------------------------------------------
// Kernel 2: elementwise hi/lo split (x, h_prev)
// ---------------------------------------------------------------------------
__global__ __launch_bounds__(256) void split_kernel(
    const float* __restrict__ src,
    __nv_bfloat16* __restrict__ dh,
    __nv_bfloat16* __restrict__ dl,
    int n4)
{
    int i = blockIdx.x * blockDim.x + threadIdx.x;
    if (i >= n4) return;
    float4 v = ((const float4*)src)[i];
    float vv[4] = {v.x, v.y, v.z, v.w};
    __nv_bfloat16 h[4], l[4];
#pragma unroll
    for (int j = 0; j < 4; ++j) {
        h[j] = __float2bfloat16(vv[j]);
        l[j] = __float2bfloat16(vv[j] - __bfloat162float(h[j]));
    }
    ((uint2*)dh)[i] = *(uint2*)h;
    ((uint2*)dl)[i] = *(uint2*)l;
}

// ---------------------------------------------------------------------------
// Kernel 3: weight transpose + split.  in: W[nblk][k][n] fp32
//           out: Th/Tl[nblk][n][k] bf16
// ---------------------------------------------------------------------------
__global__ __launch_bounds__(256) void wtrans_kernel(
    const float* __restrict__ W,
    __nv_bfloat16* __restrict__ Th,
    __nv_bfloat16* __restrict__ Tl)
{
    __shared__ float t[32][33];
    const int n0 = blockIdx.x * 32, k0 = blockIdx.y * 32, nb = blockIdx.z;
    const float* Wb = W + (size_t)nb * 512 * 512;
    const int tx = threadIdx.x, ty = threadIdx.y;   // 32 x 8
#pragma unroll
    for (int r = 0; r < 32; r += 8)
        t[ty + r][tx] = Wb[(size_t)(k0 + ty + r) * 512 + n0 + tx];
    __syncthreads();
    size_t ob = (size_t)nb * 512 * 512;
#pragma unroll
    for (int r = 0; r < 32; r += 8) {
        float v = t[tx][ty + r];
        __nv_bfloat16 h = __float2bfloat16(v);
        __nv_bfloat16 l = __float2bfloat16(v - __bfloat162float(h));
        size_t o = ob + (size_t)(n0 + ty + r) * 512 + k0 + tx;
        Th[o] = h; Tl[o] = l;
    }
}

// ---------------------------------------------------------------------------
// Kernel 4: mma.sync bf16x3 GEMM.  Tile M=128 N=128 K=1024 (W then R phase).
// grid: (4 ntile, 32 mtile, 16 = gate*4+nblk), 256 threads (8 warps, 32x64).
// smem: 2 stages x (Ah,Al,Bh,Bl each 128x32 bf16 = 8KB) = 64KB dynamic.
// ---------------------------------------------------------------------------
#define STAGE_BYTES 32768
#define OFF_AH 0
#define OFF_AL 8192
#define OFF_BH 16384
#define OFF_BL 24576
#define SMEM_TOTAL_G 65536

__global__ __launch_bounds__(256, 1) void gemm_mma_kernel()
{
    extern __shared__ __align__(128) char smem[];
    const uint32_t sbase = smem_u32(smem);
    const int tid = threadIdx.x;
    const int lane = tid & 31;
    const int wid = tid >> 5;
    const int wm = wid & 3;          // warp row  (4)  -> 32 rows each
    const int wn = wid >> 2;         // warp col  (2)  -> 64 cols each

    const int ntile = blockIdx.x, mtile = blockIdx.y;
    const int gate = blockIdx.z >> 2, nblk = blockIdx.z & 3;
    const int row0 = mtile * 128;
    const int n0 = ntile * 128;

    const __nv_bfloat16 *a1h_, *a1l_;
    if (gate == 0 || gate == 3) { a1h_ = g_xh; a1l_ = g_xl; }
    else                        { a1h_ = g_ch; a1l_ = g_cl; }
    const __nv_bfloat16* bwh = g_wt[gate][0];
    const __nv_bfloat16* bwl = g_wt[gate][1];
    const __nv_bfloat16* brh = g_wt[4 + gate][0];
    const __nv_bfloat16* brl = g_wt[4 + gate][1];

    float acc[2][8][4];
#pragma unroll
    for (int i = 0; i < 2; ++i)
#pragma unroll
        for (int j = 0; j < 8; ++j)
#pragma unroll
            for (int k = 0; k < 4; ++k) acc[i][j][k] = 0.f;

    // per-thread cp.async mapping: chunk q in 0..511 per half-tile
    // q -> row = q>>2, c = q&3
    const int q0 = tid;          // covers q = tid and tid+256

    // ---- load one k-chunk (32 k) into stage buf ----
    auto load_chunk = [&](int c, int buf) {
        const __nv_bfloat16 *Ah, *Al, *Bh, *Bl;
        int kc;
        if (c < 16) { Ah = a1h_; Al = a1l_; Bh = bwh; Bl = bwl; kc = c * 32; }
        else        { Ah = g_hh; Al = g_hl; Bh = brh; Bl = brl; kc = (c - 16) * 32; }
        const size_t aoff = (size_t)row0 * D_ + nblk * 512 + kc;
        const size_t boff = (size_t)nblk * (512 * 512) + (size_t)n0 * 512 + kc;
        const uint32_t sb = sbase + (uint32_t)buf * STAGE_BYTES;
#pragma unroll
        for (int i = 0; i < 2; ++i) {
            int q = q0 + i * 256;
            int row = q >> 2, cc = q & 3;
            uint32_t so = swz(row, cc);
            cp_async16(sb + OFF_AH + so, Ah + aoff + (size_t)row * D_ + cc * 8);
            cp_async16(sb + OFF_AL + so, Al + aoff + (size_t)row * D_ + cc * 8);
            cp_async16(sb + OFF_BH + so, Bh + boff + (size_t)row * 512 + cc * 8);
            cp_async16(sb + OFF_BL + so, Bl + boff + (size_t)row * 512 + cc * 8);
        }
    };

    // ldmatrix address precompute (lane-dependent parts)
    const int g = lane >> 3, lr = lane & 7;

    load_chunk(0, 0);
    CP_COMMIT();

#pragma unroll 1
    for (int c = 0; c < 32; ++c) {
        if (c < 31) { load_chunk(c + 1, (c + 1) & 1); CP_COMMIT(); CP_WAIT1(); }
        else        { CP_WAIT0(); }
        __syncthreads();

        const uint32_t sb = sbase + (uint32_t)(c & 1) * STAGE_BYTES;

#pragma unroll
        for (int ks = 0; ks < 2; ++ks) {
            // A fragments: rows wm*32 + mh*16 + (g&1)*8 + lr, chunk ks*2+(g>>1)
            uint32_t ah[2][4], al[2][4];
#pragma unroll
            for (int mh = 0; mh < 2; ++mh) {
                int row = wm * 32 + mh * 16 + (g & 1) * 8 + lr;
                int cc = ks * 2 + (g >> 1);
                uint32_t so = swz(row, cc);
                ldsm4(ah[mh], sb + OFF_AH + so);
                ldsm4(al[mh], sb + OFF_AL + so);
            }
            // B fragments: n rows wn*64 + nq*16 + (g>=2)*8 + lr, chunk ks*2+(g&1)
            uint32_t bh[4][4], bl[4][4];
#pragma unroll
            for (int nq = 0; nq < 4; ++nq) {
                int nrow = wn * 64 + nq * 16 + (g >> 1) * 8 + lr;
                int cc = ks * 2 + (g & 1);
                uint32_t so = swz(nrow, cc);
                ldsm4(bh[nq], sb + OFF_BH + so);
                ldsm4(bl[nq], sb + OFF_BL + so);
            }
#pragma unroll
            for (int mh = 0; mh < 2; ++mh)
#pragma unroll
                for (int nq = 0; nq < 4; ++nq)
#pragma unroll
                    for (int sub = 0; sub < 2; ++sub) {
                        float* d = acc[mh][nq * 2 + sub];
                        mma16816(d, ah[mh], &bh[nq][sub * 2]);
                        mma16816(d, ah[mh], &bl[nq][sub * 2]);
                        mma16816(d, al[mh], &bh[nq][sub * 2]);
                    }
        }
        __syncthreads();
    }

    // Epilogue: direct fp32 stores to g_pre
    float* outp = g_pre + (size_t)gate * B_ * H_;
    const int colb = nblk * 512 + n0 + wn * 64 + (lane & 3) * 2;
    const int rowb = row0 + wm * 32 + (lane >> 2);
#pragma unroll
    for (int mh = 0; mh < 2; ++mh)
#pragma unroll
        for (int n8 = 0; n8 < 8; ++n8) {
            int col = colb + n8 * 8;
            int r0 = rowb + mh * 16;
            float* p0 = outp + (size_t)r0 * H_ + col;
            float* p1 = outp + (size_t)(r0 + 8) * H_ + col;
            *(float2*)p0 = make_float2(acc[mh][n8][0], acc[mh][n8][1]);
            *(float2*)p1 = make_float2(acc[mh][n8][2], acc[mh][n8][3]);
        }
}

// ---------------------------------------------------------------------------
// Kernel 5: gates + state update
// ---------------------------------------------------------------------------
__global__ __launch_bounds__(256) void gates_kernel(
    const float* __restrict__ c_prev,
    const float* __restrict__ bz, const float* __restrict__ bi,
    const float* __restrict__ bf, const float* __restrict__ bo,
    const float* __restrict__ rbz, const float* __restrict__ rbi,
    const float* __restrict__ rbf, const float* __restrict__ rbo,
    float* __restrict__ out_h, float* __restrict__ out_c)
{
    size_t idx = (size_t)blockIdx.x * blockDim.x + threadIdx.x;
    if (idx >= (size_t)B_ * H_) return;
    int j = (int)(idx & (H_ - 1));
    const size_t n = (size_t)B_ * H_;
    float pz = g_pre[0 * n + idx] + bz[j] + rbz[j];
    float pi = g_pre[1 * n + idx] + bi[j] + rbi[j];
    float pf = g_pre[2 * n + idx] + bf[j] + rbf[j];
    float po = g_pre[3 * n + idx] + bo[j] + rbo[j];

    float z  = tanhf(pz);
    float ig = 1.f / (1.f + expf(-pi));
    float fg = 1.f / (1.f + expf(-pf));
    float og = 1.f / (1.f + expf(-po));

    float cc = fg * c_prev[idx] + ig * z;
    float hh = og * tanhf(cc);
    out_h[idx] = hh;
    out_c[idx] = cc;
}

// ---------------------------------------------------------------------------
// Launch
// ---------------------------------------------------------------------------
extern "C" void kernel_launch(void* const* d_in, const int* in_sizes, int n_in,
                              void* d_out, int out_size)
{
    const float* x      = (const float*)d_in[0];
    const float* h_prev = (const float*)d_in[1];
    const float* c_prev = (const float*)d_in[2];
    const float* ln_g   = (const float*)d_in[3];
    const float* ln_b   = (const float*)d_in[4];
    const float* conv_w = (const float*)d_in[5];
    const float* conv_b = (const float*)d_in[6];
    const float* Wmat[4] = { (const float*)d_in[7],  (const float*)d_in[9],
                             (const float*)d_in[11], (const float*)d_in[13] };
    const float* bz  = (const float*)d_in[8],  *bi  = (const float*)d_in[10];
    const float* bf  = (const float*)d_in[12], *bo  = (const float*)d_in[14];
    const float* Rmat[4] = { (const float*)d_in[15], (const float*)d_in[17],
                             (const float*)d_in[19], (const float*)d_in[21] };
    const float* rbz = (const float*)d_in[16], *rbi = (const float*)d_in[18];
    const float* rbf = (const float*)d_in[20], *rbo = (const float*)d_in[22];

    float* out = (float*)d_out;

    cudaFuncSetAttribute(gemm_mma_kernel,
                         cudaFuncAttributeMaxDynamicSharedMemorySize, SMEM_TOTAL_G);

    void* p;
    cudaGetSymbolAddress(&p, g_xh); __nv_bfloat16* xh = (__nv_bfloat16*)p;
    cudaGetSymbolAddress(&p, g_xl); __nv_bfloat16* xl = (__nv_bfloat16*)p;
    cudaGetSymbolAddress(&p, g_hh); __nv_bfloat16* hh = (__nv_bfloat16*)p;
    cudaGetSymbolAddress(&p, g_hl); __nv_bfloat16* hl = (__nv_bfloat16*)p;
    cudaGetSymbolAddress(&p, g_wt); __nv_bfloat16* wt = (__nv_bfloat16*)p;
    const size_t WT_T = (size_t)NB_ * 512 * 512;   // elems per tensor per half

    const size_t nelem = (size_t)B_ * H_;

    // 1) LN + conv + SiLU (-> g_ch/g_cl)
    ln_conv_kernel<<<B_, 256>>>(x, ln_g, ln_b, conv_w, conv_b);

    // 2) split x and h_prev
    int n4 = (int)(((size_t)B_ * D_) / 4);
    split_kernel<<<(n4 + 255) / 256, 256>>>(x, xh, xl, n4);
    split_kernel<<<(n4 + 255) / 256, 256>>>(h_prev, hh, hl, n4);

    // 3) transpose + split weights: tensors 0..3 = W*, 4..7 = R*
    dim3 tgrid(16, 16, NB_), tblk(32, 8);
    for (int g = 0; g < 4; ++g)
        wtrans_kernel<<<tgrid, tblk>>>(Wmat[g], wt + (2 * g) * WT_T, wt + (2 * g + 1) * WT_T);
    for (int g = 0; g < 4; ++g)
        wtrans_kernel<<<tgrid, tblk>>>(Rmat[g], wt + (8 + 2 * g) * WT_T, wt + (9 + 2 * g) * WT_T);

    // 4) all GEMMs in one launch
    dim3 ggrid(4, 32, 16);
    gemm_mma_kernel<<<ggrid, 256, SMEM_TOTAL_G>>>();

    // 5) gates + state update
    gates_kernel<<<(int)((nelem + 255) / 256), 256>>>(
        c_prev, bz, bi, bf, bo, rbz, rbi, rbf, rbo, out, out + nelem);
}

// round 6
// speedup vs baseline: 2.8045x; 1.1659x over previous
#include <cuda_runtime.h>
#include <cuda_bf16.h>
#include <math.h>
#include <stdint.h>

// Problem constants
#define B_    4096
#define D_    2048
#define H_    2048
#define NB_   4
#define BIN_  512
#define BOUT_ 512
#define EPS_  1e-5f

// ---------------------------------------------------------------------------
// Device scratch (allocation-free)
// ---------------------------------------------------------------------------
__device__ __nv_bfloat16 g_xh[(size_t)B_ * D_];
__device__ __nv_bfloat16 g_xl[(size_t)B_ * D_];
__device__ __nv_bfloat16 g_ch[(size_t)B_ * D_];   // SiLU(conv(LN(x))) split
__device__ __nv_bfloat16 g_cl[(size_t)B_ * D_];
__device__ __nv_bfloat16 g_hh[(size_t)B_ * H_];
__device__ __nv_bfloat16 g_hl[(size_t)B_ * H_];
// Transposed + split weights: [tensor 0..7][hi/lo][NB*512*512], row=n, col=k
// tensors: 0..3 = Wz,Wi,Wf,Wo ; 4..7 = Rz,Ri,Rf,Ro
__device__ __nv_bfloat16 g_wt[8][2][(size_t)NB_ * 512 * 512];
__device__ float g_pre[4ull * B_ * H_];

// ---------------------------------------------------------------------------
// PTX helpers (baseline-compute_103-safe: mma.sync / ldmatrix / cp.async only)
// ---------------------------------------------------------------------------
__device__ __forceinline__ uint32_t smem_u32(const void* p) {
    uint32_t a;
    asm("{ .reg .u64 t; cvta.to.shared.u64 t, %1; cvt.u32.u64 %0, t; }"
        : "=r"(a) : "l"(p));
    return a;
}

__device__ __forceinline__ void cp_async16(uint32_t dst, const void* src) {
    asm volatile("cp.async.cg.shared.global [%0], [%1], 16;"
                 :: "r"(dst), "l"(src) : "memory");
}
#define CP_COMMIT() asm volatile("cp.async.commit_group;" ::: "memory")

__device__ __forceinline__ void ldsm4(uint32_t* r, uint32_t addr) {
    asm volatile("ldmatrix.sync.aligned.m8n8.x4.shared.b16 {%0,%1,%2,%3}, [%4];"
                 : "=r"(r[0]), "=r"(r[1]), "=r"(r[2]), "=r"(r[3]) : "r"(addr));
}

__device__ __forceinline__ void mma16816(float* d, const uint32_t* a, const uint32_t* b) {
    asm volatile(
        "mma.sync.aligned.m16n8k16.row.col.f32.bf16.bf16.f32 "
        "{%0,%1,%2,%3}, {%4,%5,%6,%7}, {%8,%9}, {%0,%1,%2,%3};"
        : "+f"(d[0]), "+f"(d[1]), "+f"(d[2]), "+f"(d[3])
        : "r"(a[0]), "r"(a[1]), "r"(a[2]), "r"(a[3]), "r"(b[0]), "r"(b[1]));
}

// swizzled 16B-chunk offset inside a (rows x 64B) tile
__device__ __forceinline__ uint32_t swz(int row, int c) {
    return (uint32_t)(row * 64 + ((c ^ ((row >> 1) & 3)) << 4));
}

// ---------------------------------------------------------------------------
// Kernel 1: LayerNorm + causal conv3 + SiLU; writes bf16 hi/lo split directly
// ---------------------------------------------------------------------------
__global__ __launch_bounds__(256) void ln_conv_kernel(
    const float* __restrict__ x,
    const float* __restrict__ ln_g,
    const float* __restrict__ ln_b,
    const float* __restrict__ conv_w,
    const float* __restrict__ conv_b)
{
    __shared__ float xn[D_];
    __shared__ float red[256];

    const int row = blockIdx.x;
    const int tid = threadIdx.x;
    const float* xr = x + (size_t)row * D_;

    float v[8];
    float s = 0.f, ss = 0.f;
#pragma unroll
    for (int i = 0; i < 8; ++i) {
        float t = xr[tid + i * 256];
        v[i] = t; s += t; ss += t * t;
    }
    red[tid] = s; __syncthreads();
    for (int off = 128; off > 0; off >>= 1) {
        if (tid < off) red[tid] += red[tid + off];
        __syncthreads();
    }
    const float mean = red[0] * (1.0f / D_);
    __syncthreads();
    red[tid] = ss; __syncthreads();
    for (int off = 128; off > 0; off >>= 1) {
        if (tid < off) red[tid] += red[tid + off];
        __syncthreads();
    }
    const float var = red[0] * (1.0f / D_) - mean * mean;
    const float rstd = rsqrtf(var + EPS_);
    __syncthreads();

#pragma unroll
    for (int i = 0; i < 8; ++i) {
        int d = tid + i * 256;
        xn[d] = (v[i] - mean) * rstd * ln_g[d] + ln_b[d];
    }
    __syncthreads();

    const float w0 = conv_w[0], w1 = conv_w[1], w2 = conv_w[2], cb = conv_b[0];
    size_t base = (size_t)row * D_;
#pragma unroll
    for (int i = 0; i < 8; ++i) {
        int d = tid + i * 256;
        float a0 = (d >= 2) ? xn[d - 2] : 0.f;
        float a1 = (d >= 1) ? xn[d - 1] : 0.f;
        float xc = w0 * a0 + w1 * a1 + w2 * xn[d] + cb;
        float sg = 1.f / (1.f + expf(-xc));
        float val = xc * sg;
        __nv_bfloat16 hi = __float2bfloat16(val);
        __nv_bfloat16 lo = __float2bfloat16(val - __bfloat162float(hi));
        g_ch[base + d] = hi;
        g_cl[base + d] = lo;
    }
}

// ---------------------------------------------------------------------------
// Kernel 2: elementwise hi/lo split (x, h_prev)
// ---------------------------------------------------------------------------
__global__ __launch_bounds__(256) void split_kernel(
    const float* __restrict__ src,
    __nv_bfloat16* __restrict__ dh,
    __nv_bfloat16* __restrict__ dl,
    int n4)
{
    int i = blockIdx.x * blockDim.x + threadIdx.x;
    if (i >= n4) return;
    float4 v = ((const float4*)src)[i];
    float vv[4] = {v.x, v.y, v.z, v.w};
    __nv_bfloat16 h[4], l[4];
#pragma unroll
    for (int j = 0; j < 4; ++j) {
        h[j] = __float2bfloat16(vv[j]);
        l[j] = __float2bfloat16(vv[j] - __bfloat162float(h[j]));
    }
    ((uint2*)dh)[i] = *(uint2*)h;
    ((uint2*)dl)[i] = *(uint2*)l;
}

// ---------------------------------------------------------------------------
// Kernel 3: weight transpose + split for 4 tensors in one launch.
// grid z = t*4 + nb, t in 0..3.  in: W[t][nblk][k][n] fp32 -> out hi/lo [n][k]
// ---------------------------------------------------------------------------
__global__ __launch_bounds__(256) void wtrans4_kernel(
    const float* __restrict__ W0, const float* __restrict__ W1,
    const float* __restrict__ W2, const float* __restrict__ W3,
    __nv_bfloat16* __restrict__ outbase)   // points at g_wt[toff][0][0]
{
    __shared__ float t[32][33];
    const int n0 = blockIdx.x * 32, k0 = blockIdx.y * 32;
    const int tens = blockIdx.z >> 2, nb = blockIdx.z & 3;
    const float* Wsel = (tens == 0) ? W0 : (tens == 1) ? W1 : (tens == 2) ? W2 : W3;
    const float* Wb = Wsel + (size_t)nb * 512 * 512;
    const size_t WT_T = (size_t)NB_ * 512 * 512;
    __nv_bfloat16* Th = outbase + (size_t)(2 * tens) * WT_T;
    __nv_bfloat16* Tl = outbase + (size_t)(2 * tens + 1) * WT_T;

    const int tx = threadIdx.x, ty = threadIdx.y;   // 32 x 8
#pragma unroll
    for (int r = 0; r < 32; r += 8)
        t[ty + r][tx] = Wb[(size_t)(k0 + ty + r) * 512 + n0 + tx];
    __syncthreads();
    size_t ob = (size_t)nb * 512 * 512;
#pragma unroll
    for (int r = 0; r < 32; r += 8) {
        float v = t[tx][ty + r];
        __nv_bfloat16 h = __float2bfloat16(v);
        __nv_bfloat16 l = __float2bfloat16(v - __bfloat162float(h));
        size_t o = ob + (size_t)(n0 + ty + r) * 512 + k0 + tx;
        Th[o] = h; Tl[o] = l;
    }
}

// ---------------------------------------------------------------------------
// Kernel 4: mma.sync bf16x3 GEMM.  Tile M=256 N=128 K=1024 (W then R phase).
// grid: (4 ntile, 16 mtile, 16 = gate*4+nblk), 512 threads (16 warps, 64x32).
// smem: 3 stages x (Ah 16K, Al 16K, Bh 8K, Bl 8K) = 144KB dynamic.
// ---------------------------------------------------------------------------
#define STAGE_BYTES 49152
#define OFF_AH 0
#define OFF_AL 16384
#define OFF_BH 32768
#define OFF_BL 40960
#define SMEM_TOTAL_G (3 * STAGE_BYTES)

__global__ __launch_bounds__(512, 1) void gemm_mma_kernel()
{
    extern __shared__ __align__(128) char smem[];
    const uint32_t sbase = smem_u32(smem);
    const int tid = threadIdx.x;
    const int lane = tid & 31;
    const int wid = tid >> 5;
    const int wm = wid & 3;          // warp row  (4) -> 64 rows each
    const int wn = wid >> 2;         // warp col  (4) -> 32 cols each

    const int ntile = blockIdx.x, mtile = blockIdx.y;
    const int gate = blockIdx.z >> 2, nblk = blockIdx.z & 3;
    const int row0 = mtile * 256;
    const int n0 = ntile * 128;

    const __nv_bfloat16 *a1h_, *a1l_;
    if (gate == 0 || gate == 3) { a1h_ = g_xh; a1l_ = g_xl; }
    else                        { a1h_ = g_ch; a1l_ = g_cl; }
    const __nv_bfloat16* bwh = g_wt[gate][0];
    const __nv_bfloat16* bwl = g_wt[gate][1];
    const __nv_bfloat16* brh = g_wt[4 + gate][0];
    const __nv_bfloat16* brl = g_wt[4 + gate][1];

    float acc[4][4][4];   // mh (16-row blocks), n8 (8-col blocks), frag
#pragma unroll
    for (int i = 0; i < 4; ++i)
#pragma unroll
        for (int j = 0; j < 4; ++j)
#pragma unroll
            for (int k = 0; k < 4; ++k) acc[i][j][k] = 0.f;

    // ---- load one k-chunk (32 k) into stage buf ----
    auto load_chunk = [&](int c, int buf) {
        const __nv_bfloat16 *Ah, *Al, *Bh, *Bl;
        int kc;
        if (c < 16) { Ah = a1h_; Al = a1l_; Bh = bwh; Bl = bwl; kc = c * 32; }
        else        { Ah = g_hh; Al = g_hl; Bh = brh; Bl = brl; kc = (c - 16) * 32; }
        const size_t aoff = (size_t)row0 * D_ + nblk * 512 + kc;
        const size_t boff = (size_t)nblk * (512 * 512) + (size_t)n0 * 512 + kc;
        const uint32_t sb = sbase + (uint32_t)buf * STAGE_BYTES;
        // A: 256 rows x 4 chunks per half = 1024 chunks/half; 2 per thread
#pragma unroll
        for (int i = 0; i < 2; ++i) {
            int q = tid + i * 512;
            int row = q >> 2, cc = q & 3;
            uint32_t so = swz(row, cc);
            const size_t ga = aoff + (size_t)row * D_ + cc * 8;
            cp_async16(sb + OFF_AH + so, Ah + ga);
            cp_async16(sb + OFF_AL + so, Al + ga);
        }
        // B: 128 rows x 4 chunks per half = 512 chunks/half; 1 per thread
        {
            int row = tid >> 2, cc = tid & 3;
            uint32_t so = swz(row, cc);
            const size_t gb = boff + (size_t)row * 512 + cc * 8;
            cp_async16(sb + OFF_BH + so, Bh + gb);
            cp_async16(sb + OFF_BL + so, Bl + gb);
        }
    };

    const int g = lane >> 3, lr = lane & 7;

    load_chunk(0, 0); CP_COMMIT();
    load_chunk(1, 1); CP_COMMIT();

#pragma unroll 1
    for (int c = 0; c < 32; ++c) {
        if (c + 2 < 32) {
            load_chunk(c + 2, (c + 2) % 3);
            CP_COMMIT();
            asm volatile("cp.async.wait_group 2;" ::: "memory");
        } else if (c == 30) {
            asm volatile("cp.async.wait_group 1;" ::: "memory");
        } else {
            asm volatile("cp.async.wait_group 0;" ::: "memory");
        }
        __syncthreads();

        const uint32_t sb = sbase + (uint32_t)(c % 3) * STAGE_BYTES;

#pragma unroll
        for (int ks = 0; ks < 2; ++ks) {
            // B fragments for this warp's 32 columns: 2 n16 groups
            uint32_t bh[2][4], bl[2][4];
#pragma unroll
            for (int nq = 0; nq < 2; ++nq) {
                int nrow = wn * 32 + nq * 16 + (g >> 1) * 8 + lr;
                int cc = ks * 2 + (g & 1);
                uint32_t so = swz(nrow, cc);
                ldsm4(bh[nq], sb + OFF_BH + so);
                ldsm4(bl[nq], sb + OFF_BL + so);
            }
#pragma unroll
            for (int mh = 0; mh < 4; ++mh) {
                uint32_t ah[4], al[4];
                int row = wm * 64 + mh * 16 + (g & 1) * 8 + lr;
                int cc = ks * 2 + (g >> 1);
                uint32_t so = swz(row, cc);
                ldsm4(ah, sb + OFF_AH + so);
                ldsm4(al, sb + OFF_AL + so);
#pragma unroll
                for (int nq = 0; nq < 2; ++nq)
#pragma unroll
                    for (int sub = 0; sub < 2; ++sub) {
                        float* d = acc[mh][nq * 2 + sub];
                        mma16816(d, ah, &bh[nq][sub * 2]);
                        mma16816(d, ah, &bl[nq][sub * 2]);
                        mma16816(d, al, &bh[nq][sub * 2]);
                    }
            }
        }
        __syncthreads();
    }

    // Epilogue: direct fp32 stores to g_pre
    float* outp = g_pre + (size_t)gate * B_ * H_;
    const int colb = nblk * 512 + n0 + wn * 32 + (lane & 3) * 2;
    const int rowb = row0 + wm * 64 + (lane >> 2);
#pragma unroll
    for (int mh = 0; mh < 4; ++mh)
#pragma unroll
        for (int n8 = 0; n8 < 4; ++n8) {
            int col = colb + n8 * 8;
            int r0 = rowb + mh * 16;
            float* p0 = outp + (size_t)r0 * H_ + col;
            float* p1 = outp + (size_t)(r0 + 8) * H_ + col;
            *(float2*)p0 = make_float2(acc[mh][n8][0], acc[mh][n8][1]);
            *(float2*)p1 = make_float2(acc[mh][n8][2], acc[mh][n8][3]);
        }
}

// ---------------------------------------------------------------------------
// Kernel 5: gates + state update (float4 vectorized)
// ---------------------------------------------------------------------------
__global__ __launch_bounds__(256) void gates_kernel(
    const float* __restrict__ c_prev,
    const float* __restrict__ bz, const float* __restrict__ bi,
    const float* __restrict__ bf, const float* __restrict__ bo,
    const float* __restrict__ rbz, const float* __restrict__ rbi,
    const float* __restrict__ rbf, const float* __restrict__ rbo,
    float* __restrict__ out_h, float* __restrict__ out_c)
{
    const size_t n4 = (size_t)B_ * H_ / 4;
    size_t i = (size_t)blockIdx.x * blockDim.x + threadIdx.x;
    if (i >= n4) return;
    const size_t n = (size_t)B_ * H_;
    int j4 = (int)((i * 4) & (H_ - 1));   // column of first lane

    float4 pz4 = ((const float4*)(g_pre + 0 * n))[i];
    float4 pi4 = ((const float4*)(g_pre + 1 * n))[i];
    float4 pf4 = ((const float4*)(g_pre + 2 * n))[i];
    float4 po4 = ((const float4*)(g_pre + 3 * n))[i];
    float4 cp4 = ((const float4*)c_prev)[i];
    float4 bz4 = *(const float4*)(bz + j4), rz4 = *(const float4*)(rbz + j4);
    float4 bi4 = *(const float4*)(bi + j4), ri4 = *(const float4*)(rbi + j4);
    float4 bf4 = *(const float4*)(bf + j4), rf4 = *(const float4*)(rbf + j4);
    float4 bo4 = *(const float4*)(bo + j4), ro4 = *(const float4*)(rbo + j4);

    float h[4], cc[4];
    float pzv[4] = {pz4.x + bz4.x + rz4.x, pz4.y + bz4.y + rz4.y,
                    pz4.z + bz4.z + rz4.z, pz4.w + bz4.w + rz4.w};
    float piv[4] = {pi4.x + bi4.x + ri4.x, pi4.y + bi4.y + ri4.y,
                    pi4.z + bi4.z + ri4.z, pi4.w + bi4.w + ri4.w};
    float pfv[4] = {pf4.x + bf4.x + rf4.x, pf4.y + bf4.y + rf4.y,
                    pf4.z + bf4.z + rf4.z, pf4.w + bf4.w + rf4.w};
    float pov[4] = {po4.x + bo4.x + ro4.x, po4.y + bo4.y + ro4.y,
                    po4.z + bo4.z + ro4.z, po4.w + bo4.w + ro4.w};
    float cpv[4] = {cp4.x, cp4.y, cp4.z, cp4.w};
#pragma unroll
    for (int k = 0; k < 4; ++k) {
        float z  = tanhf(pzv[k]);
        float ig = 1.f / (1.f + expf(-piv[k]));
        float fg = 1.f / (1.f + expf(-pfv[k]));
        float og = 1.f / (1.f + expf(-pov[k]));
        cc[k] = fg * cpv[k] + ig * z;
        h[k]  = og * tanhf(cc[k]);
    }
    ((float4*)out_h)[i] = make_float4(h[0], h[1], h[2], h[3]);
    ((float4*)out_c)[i] = make_float4(cc[0], cc[1], cc[2], cc[3]);
}

// ---------------------------------------------------------------------------
// Launch
// ---------------------------------------------------------------------------
extern "C" void kernel_launch(void* const* d_in, const int* in_sizes, int n_in,
                              void* d_out, int out_size)
{
    const float* x      = (const float*)d_in[0];
    const float* h_prev = (const float*)d_in[1];
    const float* c_prev = (const float*)d_in[2];
    const float* ln_g   = (const float*)d_in[3];
    const float* ln_b   = (const float*)d_in[4];
    const float* conv_w = (const float*)d_in[5];
    const float* conv_b = (const float*)d_in[6];
    const float* Wz = (const float*)d_in[7],  *bz  = (const float*)d_in[8];
    const float* Wi = (const float*)d_in[9],  *bi  = (const float*)d_in[10];
    const float* Wf = (const float*)d_in[11], *bf  = (const float*)d_in[12];
    const float* Wo = (const float*)d_in[13], *bo  = (const float*)d_in[14];
    const float* Rz = (const float*)d_in[15], *rbz = (const float*)d_in[16];
    const float* Ri = (const float*)d_in[17], *rbi = (const float*)d_in[18];
    const float* Rf = (const float*)d_in[19], *rbf = (const float*)d_in[20];
    const float* Ro = (const float*)d_in[21], *rbo = (const float*)d_in[22];

    float* out = (float*)d_out;

    cudaFuncSetAttribute(gemm_mma_kernel,
                         cudaFuncAttributeMaxDynamicSharedMemorySize, SMEM_TOTAL_G);

    void* p;
    cudaGetSymbolAddress(&p, g_xh); __nv_bfloat16* xh = (__nv_bfloat16*)p;
    cudaGetSymbolAddress(&p, g_xl); __nv_bfloat16* xl = (__nv_bfloat16*)p;
    cudaGetSymbolAddress(&p, g_hh); __nv_bfloat16* hh = (__nv_bfloat16*)p;
    cudaGetSymbolAddress(&p, g_hl); __nv_bfloat16* hl = (__nv_bfloat16*)p;
    cudaGetSymbolAddress(&p, g_wt); __nv_bfloat16* wt = (__nv_bfloat16*)p;
    const size_t WT_T = (size_t)NB_ * 512 * 512;

    const size_t nelem = (size_t)B_ * H_;

    // launch 1: LN + conv + SiLU (-> g_ch/g_cl)
    ln_conv_kernel<<<B_, 256>>>(x, ln_g, ln_b, conv_w, conv_b);

    // launches 2-3: split x and h_prev
    int n4 = (int)(((size_t)B_ * D_) / 4);
    split_kernel<<<(n4 + 255) / 256, 256>>>(x, xh, xl, n4);
    split_kernel<<<(n4 + 255) / 256, 256>>>(h_prev, hh, hl, n4);

    // launches 4-5: transpose + split weights (W group, R group)
    dim3 tgrid(16, 16, 16), tblk(32, 8);
    wtrans4_kernel<<<tgrid, tblk>>>(Wz, Wi, Wf, Wo, wt);
    wtrans4_kernel<<<tgrid, tblk>>>(Rz, Ri, Rf, Ro, wt + 8 * WT_T);

    // launch 6: all GEMMs (profiled by ncu -s 5 -c 1)
    dim3 ggrid(4, 16, 16);
    gemm_mma_kernel<<<ggrid, 512, SMEM_TOTAL_G>>>();

    // launch 7: gates + state update
    gates_kernel<<<(int)((nelem / 4 + 255) / 256), 256>>>(
        c_prev, bz, bi, bf, bo, rbz, rbi, rbf, rbo, out, out + nelem);
}

// round 7
// speedup vs baseline: 4.9936x; 1.7806x over previous
#include <cuda_runtime.h>
#include <cuda_fp16.h>
#include <math.h>
#include <stdint.h>

// Problem constants
#define B_    4096
#define D_    2048
#define H_    2048
#define NB_   4
#define BIN_  512
#define BOUT_ 512
#define EPS_  1e-5f

// ---------------------------------------------------------------------------
// Device scratch (allocation-free)
// ---------------------------------------------------------------------------
__device__ __half g_x16[(size_t)B_ * D_];     // x in fp16
__device__ __half g_c16[(size_t)B_ * D_];     // SiLU(conv(LN(x))) in fp16
__device__ __half g_h16[(size_t)B_ * H_];     // h_prev in fp16
// Transposed weights: [tensor 0..7][NB*512*512] fp16, row=n, col=k
// tensors: 0..3 = Wz,Wi,Wf,Wo ; 4..7 = Rz,Ri,Rf,Ro
__device__ __half g_wt16[8][(size_t)NB_ * 512 * 512];
__device__ float g_pre[4ull * B_ * H_];

// ---------------------------------------------------------------------------
// PTX helpers (baseline-compute_103-safe: mma.sync / ldmatrix / cp.async only)
// ---------------------------------------------------------------------------
__device__ __forceinline__ uint32_t smem_u32(const void* p) {
    uint32_t a;
    asm("{ .reg .u64 t; cvta.to.shared.u64 t, %1; cvt.u32.u64 %0, t; }"
        : "=r"(a) : "l"(p));
    return a;
}

__device__ __forceinline__ void cp_async16(uint32_t dst, const void* src) {
    asm volatile("cp.async.cg.shared.global [%0], [%1], 16;"
                 :: "r"(dst), "l"(src) : "memory");
}
#define CP_COMMIT() asm volatile("cp.async.commit_group;" ::: "memory")

__device__ __forceinline__ void ldsm4(uint32_t* r, uint32_t addr) {
    asm volatile("ldmatrix.sync.aligned.m8n8.x4.shared.b16 {%0,%1,%2,%3}, [%4];"
                 : "=r"(r[0]), "=r"(r[1]), "=r"(r[2]), "=r"(r[3]) : "r"(addr));
}

__device__ __forceinline__ void mma16816(float* d, const uint32_t* a, const uint32_t* b) {
    asm volatile(
        "mma.sync.aligned.m16n8k16.row.col.f32.f16.f16.f32 "
        "{%0,%1,%2,%3}, {%4,%5,%6,%7}, {%8,%9}, {%0,%1,%2,%3};"
        : "+f"(d[0]), "+f"(d[1]), "+f"(d[2]), "+f"(d[3])
        : "r"(a[0]), "r"(a[1]), "r"(a[2]), "r"(a[3]), "r"(b[0]), "r"(b[1]));
}

// swizzled 16B-chunk offset inside a (rows x 64B) tile
__device__ __forceinline__ uint32_t swz(int row, int c) {
    return (uint32_t)(row * 64 + ((c ^ ((row >> 1) & 3)) << 4));
}

// ---------------------------------------------------------------------------
// Kernel 1: LayerNorm + causal conv3 + SiLU; writes fp16 directly
// ---------------------------------------------------------------------------
__global__ __launch_bounds__(256) void ln_conv_kernel(
    const float* __restrict__ x,
    const float* __restrict__ ln_g,
    const float* __restrict__ ln_b,
    const float* __restrict__ conv_w,
    const float* __restrict__ conv_b)
{
    __shared__ float xn[D_];
    __shared__ float red[256];

    const int row = blockIdx.x;
    const int tid = threadIdx.x;
    const float* xr = x + (size_t)row * D_;

    float v[8];
    float s = 0.f, ss = 0.f;
#pragma unroll
    for (int i = 0; i < 8; ++i) {
        float t = xr[tid + i * 256];
        v[i] = t; s += t; ss += t * t;
    }
    red[tid] = s; __syncthreads();
    for (int off = 128; off > 0; off >>= 1) {
        if (tid < off) red[tid] += red[tid + off];
        __syncthreads();
    }
    const float mean = red[0] * (1.0f / D_);
    __syncthreads();
    red[tid] = ss; __syncthreads();
    for (int off = 128; off > 0; off >>= 1) {
        if (tid < off) red[tid] += red[tid + off];
        __syncthreads();
    }
    const float var = red[0] * (1.0f / D_) - mean * mean;
    const float rstd = rsqrtf(var + EPS_);
    __syncthreads();

#pragma unroll
    for (int i = 0; i < 8; ++i) {
        int d = tid + i * 256;
        xn[d] = (v[i] - mean) * rstd * ln_g[d] + ln_b[d];
    }
    __syncthreads();

    const float w0 = conv_w[0], w1 = conv_w[1], w2 = conv_w[2], cb = conv_b[0];
    size_t base = (size_t)row * D_;
#pragma unroll
    for (int i = 0; i < 8; ++i) {
        int d = tid + i * 256;
        float a0 = (d >= 2) ? xn[d - 2] : 0.f;
        float a1 = (d >= 1) ? xn[d - 1] : 0.f;
        float xc = w0 * a0 + w1 * a1 + w2 * xn[d] + cb;
        float sg = 1.f / (1.f + expf(-xc));
        g_c16[base + d] = __float2half(xc * sg);
    }
}

// ---------------------------------------------------------------------------
// Kernel 2: fp32 -> fp16 convert
// ---------------------------------------------------------------------------
__global__ __launch_bounds__(256) void cvt_kernel(
    const float* __restrict__ src,
    __half* __restrict__ dst,
    int n4)
{
    int i = blockIdx.x * blockDim.x + threadIdx.x;
    if (i >= n4) return;
    float4 v = ((const float4*)src)[i];
    __half h[4] = { __float2half(v.x), __float2half(v.y),
                    __float2half(v.z), __float2half(v.w) };
    ((uint2*)dst)[i] = *(uint2*)h;
}

// ---------------------------------------------------------------------------
// Kernel 3: weight transpose for all 8 tensors in one launch.
// grid z = t*4 + nb, t in 0..7.  in: W[t][nblk][k][n] fp32 -> out fp16 [n][k]
// ---------------------------------------------------------------------------
__global__ __launch_bounds__(256) void wtrans8_kernel(
    const float* __restrict__ W0, const float* __restrict__ W1,
    const float* __restrict__ W2, const float* __restrict__ W3,
    const float* __restrict__ W4, const float* __restrict__ W5,
    const float* __restrict__ W6, const float* __restrict__ W7)
{
    __shared__ float t[32][33];
    const int n0 = blockIdx.x * 32, k0 = blockIdx.y * 32;
    const int tens = blockIdx.z >> 2, nb = blockIdx.z & 3;
    const float* Ws[8] = {W0, W1, W2, W3, W4, W5, W6, W7};
    const float* Wb = Ws[tens] + (size_t)nb * 512 * 512;
    __half* Th = g_wt16[tens];

    const int tx = threadIdx.x, ty = threadIdx.y;   // 32 x 8
#pragma unroll
    for (int r = 0; r < 32; r += 8)
        t[ty + r][tx] = Wb[(size_t)(k0 + ty + r) * 512 + n0 + tx];
    __syncthreads();
    size_t ob = (size_t)nb * 512 * 512;
#pragma unroll
    for (int r = 0; r < 32; r += 8) {
        float v = t[tx][ty + r];
        Th[ob + (size_t)(n0 + ty + r) * 512 + k0 + tx] = __float2half(v);
    }
}

// ---------------------------------------------------------------------------
// Kernel 4: mma.sync fp16 GEMM.  Tile M=256 N=128 K=1024 (W then R phase).
// grid: (4 ntile, 16 mtile, 16 = gate*4+nblk), 512 threads (16 warps, 64x32).
// smem: 4 stages x (A 16K + B 8K) = 96KB dynamic. One barrier per chunk.
// ---------------------------------------------------------------------------
#define STAGE_BYTES 24576
#define OFF_A 0
#define OFF_B 16384
#define SMEM_TOTAL_G (4 * STAGE_BYTES)

__global__ __launch_bounds__(512, 1) void gemm_mma_kernel()
{
    extern __shared__ __align__(128) char smem[];
    const uint32_t sbase = smem_u32(smem);
    const int tid = threadIdx.x;
    const int lane = tid & 31;
    const int wid = tid >> 5;
    const int wm = wid & 3;          // warp row  (4) -> 64 rows each
    const int wn = wid >> 2;         // warp col  (4) -> 32 cols each

    const int ntile = blockIdx.x, mtile = blockIdx.y;
    const int gate = blockIdx.z >> 2, nblk = blockIdx.z & 3;
    const int row0 = mtile * 256;
    const int n0 = ntile * 128;

    const __half* a16 = (gate == 0 || gate == 3) ? g_x16 : g_c16;
    const __half* bw = g_wt16[gate];
    const __half* br = g_wt16[4 + gate];

    float acc[4][4][4];   // mh (16-row blocks), n8 (8-col blocks), frag
#pragma unroll
    for (int i = 0; i < 4; ++i)
#pragma unroll
        for (int j = 0; j < 4; ++j)
#pragma unroll
            for (int k = 0; k < 4; ++k) acc[i][j][k] = 0.f;

    // ---- load one k-chunk (32 k) into stage buf ----
    auto load_chunk = [&](int c, int buf) {
        const __half *A, *Bw;
        int kc;
        if (c < 16) { A = a16;   Bw = bw; kc = c * 32; }
        else        { A = g_h16; Bw = br; kc = (c - 16) * 32; }
        const size_t aoff = (size_t)row0 * D_ + nblk * 512 + kc;
        const size_t boff = (size_t)nblk * (512 * 512) + (size_t)n0 * 512 + kc;
        const uint32_t sb = sbase + (uint32_t)buf * STAGE_BYTES;
        // A: 256 rows x 4 16B-chunks = 1024; 2 per thread
#pragma unroll
        for (int i = 0; i < 2; ++i) {
            int q = tid + i * 512;
            int row = q >> 2, cc = q & 3;
            cp_async16(sb + OFF_A + swz(row, cc), A + aoff + (size_t)row * D_ + cc * 8);
        }
        // B: 128 rows x 4 chunks = 512; 1 per thread
        {
            int row = tid >> 2, cc = tid & 3;
            cp_async16(sb + OFF_B + swz(row, cc), Bw + boff + (size_t)row * 512 + cc * 8);
        }
    };

    const int g = lane >> 3, lr = lane & 7;

    load_chunk(0, 0); CP_COMMIT();
    load_chunk(1, 1); CP_COMMIT();
    load_chunk(2, 2); CP_COMMIT();

#pragma unroll 1
    for (int c = 0; c < 32; ++c) {
        if (c <= 29)      asm volatile("cp.async.wait_group 2;" ::: "memory");
        else if (c == 30) asm volatile("cp.async.wait_group 1;" ::: "memory");
        else              asm volatile("cp.async.wait_group 0;" ::: "memory");
        __syncthreads();
        if (c + 3 < 32) { load_chunk(c + 3, (c + 3) & 3); CP_COMMIT(); }

        const uint32_t sb = sbase + (uint32_t)(c & 3) * STAGE_BYTES;

#pragma unroll
        for (int ks = 0; ks < 2; ++ks) {
            uint32_t bf[2][4];
#pragma unroll
            for (int nq = 0; nq < 2; ++nq) {
                int nrow = wn * 32 + nq * 16 + (g >> 1) * 8 + lr;
                ldsm4(bf[nq], sb + OFF_B + swz(nrow, ks * 2 + (g & 1)));
            }
#pragma unroll
            for (int mh = 0; mh < 4; ++mh) {
                uint32_t af[4];
                int row = wm * 64 + mh * 16 + (g & 1) * 8 + lr;
                ldsm4(af, sb + OFF_A + swz(row, ks * 2 + (g >> 1)));
#pragma unroll
                for (int nq = 0; nq < 2; ++nq)
#pragma unroll
                    for (int sub = 0; sub < 2; ++sub)
                        mma16816(acc[mh][nq * 2 + sub], af, &bf[nq][sub * 2]);
            }
        }
    }

    // Epilogue: direct fp32 stores to g_pre
    float* outp = g_pre + (size_t)gate * B_ * H_;
    const int colb = nblk * 512 + n0 + wn * 32 + (lane & 3) * 2;
    const int rowb = row0 + wm * 64 + (lane >> 2);
#pragma unroll
    for (int mh = 0; mh < 4; ++mh)
#pragma unroll
        for (int n8 = 0; n8 < 4; ++n8) {
            int col = colb + n8 * 8;
            int r0 = rowb + mh * 16;
            float* p0 = outp + (size_t)r0 * H_ + col;
            float* p1 = outp + (size_t)(r0 + 8) * H_ + col;
            *(float2*)p0 = make_float2(acc[mh][n8][0], acc[mh][n8][1]);
            *(float2*)p1 = make_float2(acc[mh][n8][2], acc[mh][n8][3]);
        }
}

// ---------------------------------------------------------------------------
// Kernel 5: gates + state update (float4 vectorized)
// ---------------------------------------------------------------------------
__global__ __launch_bounds__(256) void gates_kernel(
    const float* __restrict__ c_prev,
    const float* __restrict__ bz, const float* __restrict__ bi,
    const float* __restrict__ bf, const float* __restrict__ bo,
    const float* __restrict__ rbz, const float* __restrict__ rbi,
    const float* __restrict__ rbf, const float* __restrict__ rbo,
    float* __restrict__ out_h, float* __restrict__ out_c)
{
    const size_t n4 = (size_t)B_ * H_ / 4;
    size_t i = (size_t)blockIdx.x * blockDim.x + threadIdx.x;
    if (i >= n4) return;
    const size_t n = (size_t)B_ * H_;
    int j4 = (int)((i * 4) & (H_ - 1));

    float4 pz4 = ((const float4*)(g_pre + 0 * n))[i];
    float4 pi4 = ((const float4*)(g_pre + 1 * n))[i];
    float4 pf4 = ((const float4*)(g_pre + 2 * n))[i];
    float4 po4 = ((const float4*)(g_pre + 3 * n))[i];
    float4 cp4 = ((const float4*)c_prev)[i];
    float4 bz4 = *(const float4*)(bz + j4), rz4 = *(const float4*)(rbz + j4);
    float4 bi4 = *(const float4*)(bi + j4), ri4 = *(const float4*)(rbi + j4);
    float4 bf4 = *(const float4*)(bf + j4), rf4 = *(const float4*)(rbf + j4);
    float4 bo4 = *(const float4*)(bo + j4), ro4 = *(const float4*)(rbo + j4);

    float h[4], cc[4];
    float pzv[4] = {pz4.x + bz4.x + rz4.x, pz4.y + bz4.y + rz4.y,
                    pz4.z + bz4.z + rz4.z, pz4.w + bz4.w + rz4.w};
    float piv[4] = {pi4.x + bi4.x + ri4.x, pi4.y + bi4.y + ri4.y,
                    pi4.z + bi4.z + ri4.z, pi4.w + bi4.w + ri4.w};
    float pfv[4] = {pf4.x + bf4.x + rf4.x, pf4.y + bf4.y + rf4.y,
                    pf4.z + bf4.z + rf4.z, pf4.w + bf4.w + rf4.w};
    float pov[4] = {po4.x + bo4.x + ro4.x, po4.y + bo4.y + ro4.y,
                    po4.z + bo4.z + ro4.z, po4.w + bo4.w + ro4.w};
    float cpv[4] = {cp4.x, cp4.y, cp4.z, cp4.w};
#pragma unroll
    for (int k = 0; k < 4; ++k) {
        float z  = tanhf(pzv[k]);
        float ig = 1.f / (1.f + expf(-piv[k]));
        float fg = 1.f / (1.f + expf(-pfv[k]));
        float og = 1.f / (1.f + expf(-pov[k]));
        cc[k] = fg * cpv[k] + ig * z;
        h[k]  = og * tanhf(cc[k]);
    }
    ((float4*)out_h)[i] = make_float4(h[0], h[1], h[2], h[3]);
    ((float4*)out_c)[i] = make_float4(cc[0], cc[1], cc[2], cc[3]);
}

// ---------------------------------------------------------------------------
// Launch
// ---------------------------------------------------------------------------
extern "C" void kernel_launch(void* const* d_in, const int* in_sizes, int n_in,
                              void* d_out, int out_size)
{
    const float* x      = (const float*)d_in[0];
    const float* h_prev = (const float*)d_in[1];
    const float* c_prev = (const float*)d_in[2];
    const float* ln_g   = (const float*)d_in[3];
    const float* ln_b   = (const float*)d_in[4];
    const float* conv_w = (const float*)d_in[5];
    const float* conv_b = (const float*)d_in[6];
    const float* Wz = (const float*)d_in[7],  *bz  = (const float*)d_in[8];
    const float* Wi = (const float*)d_in[9],  *bi  = (const float*)d_in[10];
    const float* Wf = (const float*)d_in[11], *bf  = (const float*)d_in[12];
    const float* Wo = (const float*)d_in[13], *bo  = (const float*)d_in[14];
    const float* Rz = (const float*)d_in[15], *rbz = (const float*)d_in[16];
    const float* Ri = (const float*)d_in[17], *rbi = (const float*)d_in[18];
    const float* Rf = (const float*)d_in[19], *rbf = (const float*)d_in[20];
    const float* Ro = (const float*)d_in[21], *rbo = (const float*)d_in[22];

    float* out = (float*)d_out;

    cudaFuncSetAttribute(gemm_mma_kernel,
                         cudaFuncAttributeMaxDynamicSharedMemorySize, SMEM_TOTAL_G);

    void* p;
    cudaGetSymbolAddress(&p, g_x16); __half* x16 = (__half*)p;
    cudaGetSymbolAddress(&p, g_h16); __half* h16 = (__half*)p;

    const size_t nelem = (size_t)B_ * H_;

    // launch 1: LN + conv + SiLU (-> g_c16)
    ln_conv_kernel<<<B_, 256>>>(x, ln_g, ln_b, conv_w, conv_b);

    // launches 2-3: convert x and h_prev to fp16
    int n4 = (int)(((size_t)B_ * D_) / 4);
    cvt_kernel<<<(n4 + 255) / 256, 256>>>(x, x16, n4);
    cvt_kernel<<<(n4 + 255) / 256, 256>>>(h_prev, h16, n4);

    // launch 4: transpose all 8 weight tensors
    dim3 tgrid(16, 16, 32), tblk(32, 8);
    wtrans8_kernel<<<tgrid, tblk>>>(Wz, Wi, Wf, Wo, Rz, Ri, Rf, Ro);

    // launch 5: all GEMMs
    dim3 ggrid(4, 16, 16);
    gemm_mma_kernel<<<ggrid, 512, SMEM_TOTAL_G>>>();

    // launch 6: gates + state update
    gates_kernel<<<(int)((nelem / 4 + 255) / 256), 256>>>(
        c_prev, bz, bi, bf, bo, rbz, rbi, rbf, rbo, out, out + nelem);
}

// round 8
// speedup vs baseline: 5.3693x; 1.0752x over previous
#include <cuda_runtime.h>
#include <cuda_fp16.h>
#include <math.h>
#include <stdint.h>

// Problem constants
#define B_    4096
#define D_    2048
#define H_    2048
#define NB_   4
#define BIN_  512
#define BOUT_ 512
#define EPS_  1e-5f

// ---------------------------------------------------------------------------
// Device scratch (allocation-free)
// ---------------------------------------------------------------------------
__device__ __half g_x16[(size_t)B_ * D_];     // x in fp16
__device__ __half g_c16[(size_t)B_ * D_];     // SiLU(conv(LN(x))) in fp16
__device__ __half g_h16[(size_t)B_ * H_];     // h_prev in fp16
// Transposed weights: [tensor 0..7][NB*512*512] fp16, row=n, col=k
__device__ __half g_wt16[8][(size_t)NB_ * 512 * 512];
__device__ float g_pre[4ull * B_ * H_];

// ---------------------------------------------------------------------------
// PTX helpers
// ---------------------------------------------------------------------------
__device__ __forceinline__ uint32_t smem_u32(const void* p) {
    uint32_t a;
    asm("{ .reg .u64 t; cvta.to.shared.u64 t, %1; cvt.u32.u64 %0, t; }"
        : "=r"(a) : "l"(p));
    return a;
}

__device__ __forceinline__ void cp_async16(uint32_t dst, const void* src) {
    asm volatile("cp.async.cg.shared.global [%0], [%1], 16;"
                 :: "r"(dst), "l"(src) : "memory");
}
#define CP_COMMIT() asm volatile("cp.async.commit_group;" ::: "memory")

__device__ __forceinline__ void ldsm4(uint32_t* r, uint32_t addr) {
    asm volatile("ldmatrix.sync.aligned.m8n8.x4.shared.b16 {%0,%1,%2,%3}, [%4];"
                 : "=r"(r[0]), "=r"(r[1]), "=r"(r[2]), "=r"(r[3]) : "r"(addr));
}

__device__ __forceinline__ void mma16816(float* d, const uint32_t* a, const uint32_t* b) {
    asm volatile(
        "mma.sync.aligned.m16n8k16.row.col.f32.f16.f16.f32 "
        "{%0,%1,%2,%3}, {%4,%5,%6,%7}, {%8,%9}, {%0,%1,%2,%3};"
        : "+f"(d[0]), "+f"(d[1]), "+f"(d[2]), "+f"(d[3])
        : "r"(a[0]), "r"(a[1]), "r"(a[2]), "r"(a[3]), "r"(b[0]), "r"(b[1]));
}

// swizzled 16B-chunk offset inside a (rows x 64B) tile
__device__ __forceinline__ uint32_t swz(int row, int c) {
    return (uint32_t)(row * 64 + ((c ^ ((row >> 1) & 3)) << 4));
}

// ---------------------------------------------------------------------------
// Kernel 1: LayerNorm + causal conv3 + SiLU; writes fp16 directly
// ---------------------------------------------------------------------------
__global__ __launch_bounds__(256) void ln_conv_kernel(
    const float* __restrict__ x,
    const float* __restrict__ ln_g,
    const float* __restrict__ ln_b,
    const float* __restrict__ conv_w,
    const float* __restrict__ conv_b)
{
    __shared__ float xn[D_];
    __shared__ float red[256];

    const int row = blockIdx.x;
    const int tid = threadIdx.x;
    const float* xr = x + (size_t)row * D_;

    float v[8];
    float s = 0.f, ss = 0.f;
#pragma unroll
    for (int i = 0; i < 8; ++i) {
        float t = xr[tid + i * 256];
        v[i] = t; s += t; ss += t * t;
    }
    red[tid] = s; __syncthreads();
    for (int off = 128; off > 0; off >>= 1) {
        if (tid < off) red[tid] += red[tid + off];
        __syncthreads();
    }
    const float mean = red[0] * (1.0f / D_);
    __syncthreads();
    red[tid] = ss; __syncthreads();
    for (int off = 128; off > 0; off >>= 1) {
        if (tid < off) red[tid] += red[tid + off];
        __syncthreads();
    }
    const float var = red[0] * (1.0f / D_) - mean * mean;
    const float rstd = rsqrtf(var + EPS_);
    __syncthreads();

#pragma unroll
    for (int i = 0; i < 8; ++i) {
        int d = tid + i * 256;
        xn[d] = (v[i] - mean) * rstd * ln_g[d] + ln_b[d];
    }
    __syncthreads();

    const float w0 = conv_w[0], w1 = conv_w[1], w2 = conv_w[2], cb = conv_b[0];
    size_t base = (size_t)row * D_;
#pragma unroll
    for (int i = 0; i < 8; ++i) {
        int d = tid + i * 256;
        float a0 = (d >= 2) ? xn[d - 2] : 0.f;
        float a1 = (d >= 1) ? xn[d - 1] : 0.f;
        float xc = w0 * a0 + w1 * a1 + w2 * xn[d] + cb;
        float sg = 1.f / (1.f + expf(-xc));
        g_c16[base + d] = __float2half(xc * sg);
    }
}

// ---------------------------------------------------------------------------
// Kernel 2: fp32 -> fp16 convert for x and h_prev (one launch, blockIdx.y)
// ---------------------------------------------------------------------------
__global__ __launch_bounds__(256) void cvt2_kernel(
    const float* __restrict__ xsrc, const float* __restrict__ hsrc,
    __half* __restrict__ xdst, __half* __restrict__ hdst, int n4)
{
    int i = blockIdx.x * blockDim.x + threadIdx.x;
    if (i >= n4) return;
    const float* src = blockIdx.y ? hsrc : xsrc;
    __half* dst = blockIdx.y ? hdst : xdst;
    float4 v = ((const float4*)src)[i];
    __half h[4] = { __float2half(v.x), __float2half(v.y),
                    __float2half(v.z), __float2half(v.w) };
    ((uint2*)dst)[i] = *(uint2*)h;
}

// ---------------------------------------------------------------------------
// Kernel 3: weight transpose+cvt, 64x64 tiles, vectorized 16B stores.
// grid: (8 n-tiles, 8 k-tiles, 32 = t*4+nb). in W[t][nb][k][n] fp32 -> [n][k] fp16
// ---------------------------------------------------------------------------
__global__ __launch_bounds__(256) void wtrans8_kernel(
    const float* __restrict__ W0, const float* __restrict__ W1,
    const float* __restrict__ W2, const float* __restrict__ W3,
    const float* __restrict__ W4, const float* __restrict__ W5,
    const float* __restrict__ W6, const float* __restrict__ W7)
{
    __shared__ __half tr[64][72];   // row stride 144B (16B-aligned)
    const int n0 = blockIdx.x * 64, k0 = blockIdx.y * 64;
    const int tens = blockIdx.z >> 2, nb = blockIdx.z & 3;
    const float* Ws[8] = {W0, W1, W2, W3, W4, W5, W6, W7};
    const float* Wb = Ws[tens] + (size_t)nb * 512 * 512;
    __half* Th = g_wt16[tens] + (size_t)nb * 512 * 512;

    const int tid = threadIdx.x;
#pragma unroll
    for (int it = 0; it < 4; ++it) {
        int t = tid + it * 256;
        int k = t >> 4, nq = (t & 15) * 4;
        float4 v = *(const float4*)(Wb + (size_t)(k0 + k) * 512 + n0 + nq);
        tr[nq + 0][k] = __float2half(v.x);
        tr[nq + 1][k] = __float2half(v.y);
        tr[nq + 2][k] = __float2half(v.z);
        tr[nq + 3][k] = __float2half(v.w);
    }
    __syncthreads();
#pragma unroll
    for (int it = 0; it < 2; ++it) {
        int s = tid + it * 256;
        int n = s >> 3, ch = (s & 7) * 8;
        uint4 val = *(const uint4*)&tr[n][ch];
        *(uint4*)(Th + (size_t)(n0 + n) * 512 + k0 + ch) = val;
    }
}

// ---------------------------------------------------------------------------
// Kernel 4: mma.sync fp16 GEMM.  CTA tile M=256 N=128 K=1024 (W then R phase).
// grid: (4 ntile, 16 mtile, 16 = gate*4+nblk), 256 threads (8 warps, 64x64).
// smem: 4 stages x (A 16K + B 8K) = 96KB dynamic.
// ---------------------------------------------------------------------------
#define STAGE_BYTES 24576
#define OFF_A 0
#define OFF_B 16384
#define SMEM_TOTAL_G (4 * STAGE_BYTES)

__global__ __launch_bounds__(256, 1) void gemm_mma_kernel()
{
    extern __shared__ __align__(128) char smem[];
    const uint32_t sbase = smem_u32(smem);
    const int tid = threadIdx.x;
    const int lane = tid & 31;
    const int wid = tid >> 5;
    const int wm = wid & 3;          // warp row (4) -> 64 rows each
    const int wn = wid >> 2;         // warp col (2) -> 64 cols each

    const int ntile = blockIdx.x, mtile = blockIdx.y;
    const int gate = blockIdx.z >> 2, nblk = blockIdx.z & 3;
    const int row0 = mtile * 256;
    const int n0 = ntile * 128;

    const __half* a16 = (gate == 0 || gate == 3) ? g_x16 : g_c16;
    const __half* bw = g_wt16[gate];
    const __half* br = g_wt16[4 + gate];

    float acc[4][8][4];   // mh (16-row), n8 (8-col), frag
#pragma unroll
    for (int i = 0; i < 4; ++i)
#pragma unroll
        for (int j = 0; j < 8; ++j)
#pragma unroll
            for (int k = 0; k < 4; ++k) acc[i][j][k] = 0.f;

    // ---- load one k-chunk (32 k) into stage buf ----
    auto load_chunk = [&](int c, int buf) {
        const __half *A, *Bw;
        int kc;
        if (c < 16) { A = a16;   Bw = bw; kc = c * 32; }
        else        { A = g_h16; Bw = br; kc = (c - 16) * 32; }
        const size_t aoff = (size_t)row0 * D_ + nblk * 512 + kc;
        const size_t boff = (size_t)nblk * (512 * 512) + (size_t)n0 * 512 + kc;
        const uint32_t sb = sbase + (uint32_t)buf * STAGE_BYTES;
        // A: 256 rows x 4 16B-chunks = 1024; 4 per thread
#pragma unroll
        for (int i = 0; i < 4; ++i) {
            int q = tid + i * 256;
            int row = q >> 2, cc = q & 3;
            cp_async16(sb + OFF_A + swz(row, cc), A + aoff + (size_t)row * D_ + cc * 8);
        }
        // B: 128 rows x 4 chunks = 512; 2 per thread
#pragma unroll
        for (int i = 0; i < 2; ++i) {
            int q = tid + i * 256;
            int row = q >> 2, cc = q & 3;
            cp_async16(sb + OFF_B + swz(row, cc), Bw + boff + (size_t)row * 512 + cc * 8);
        }
    };

    const int g = lane >> 3, lr = lane & 7;

    load_chunk(0, 0); CP_COMMIT();
    load_chunk(1, 1); CP_COMMIT();
    load_chunk(2, 2); CP_COMMIT();

#pragma unroll 1
    for (int c = 0; c < 32; ++c) {
        if (c <= 29)      asm volatile("cp.async.wait_group 2;" ::: "memory");
        else if (c == 30) asm volatile("cp.async.wait_group 1;" ::: "memory");
        else              asm volatile("cp.async.wait_group 0;" ::: "memory");
        __syncthreads();
        if (c + 3 < 32) { load_chunk(c + 3, (c + 3) & 3); CP_COMMIT(); }

        const uint32_t sb = sbase + (uint32_t)(c & 3) * STAGE_BYTES;

#pragma unroll
        for (int ks = 0; ks < 2; ++ks) {
            uint32_t bf[4][4];
#pragma unroll
            for (int nq = 0; nq < 4; ++nq) {
                int nrow = wn * 64 + nq * 16 + (g >> 1) * 8 + lr;
                ldsm4(bf[nq], sb + OFF_B + swz(nrow, ks * 2 + (g & 1)));
            }
#pragma unroll
            for (int mh = 0; mh < 4; ++mh) {
                uint32_t af[4];
                int row = wm * 64 + mh * 16 + (g & 1) * 8 + lr;
                ldsm4(af, sb + OFF_A + swz(row, ks * 2 + (g >> 1)));
#pragma unroll
                for (int nq = 0; nq < 4; ++nq)
#pragma unroll
                    for (int sub = 0; sub < 2; ++sub)
                        mma16816(acc[mh][nq * 2 + sub], af, &bf[nq][sub * 2]);
            }
        }
    }

    // Epilogue: direct fp32 stores to g_pre
    float* outp = g_pre + (size_t)gate * B_ * H_;
    const int colb = nblk * 512 + n0 + wn * 64 + (lane & 3) * 2;
    const int rowb = row0 + wm * 64 + (lane >> 2);
#pragma unroll
    for (int mh = 0; mh < 4; ++mh)
#pragma unroll
        for (int n8 = 0; n8 < 8; ++n8) {
            int col = colb + n8 * 8;
            int r0 = rowb + mh * 16;
            float* p0 = outp + (size_t)r0 * H_ + col;
            float* p1 = outp + (size_t)(r0 + 8) * H_ + col;
            *(float2*)p0 = make_float2(acc[mh][n8][0], acc[mh][n8][1]);
            *(float2*)p1 = make_float2(acc[mh][n8][2], acc[mh][n8][3]);
        }
}

// ---------------------------------------------------------------------------
// Kernel 5: gates + state update (float4 vectorized)
// ---------------------------------------------------------------------------
__global__ __launch_bounds__(256) void gates_kernel(
    const float* __restrict__ c_prev,
    const float* __restrict__ bz, const float* __restrict__ bi,
    const float* __restrict__ bf, const float* __restrict__ bo,
    const float* __restrict__ rbz, const float* __restrict__ rbi,
    const float* __restrict__ rbf, const float* __restrict__ rbo,
    float* __restrict__ out_h, float* __restrict__ out_c)
{
    const size_t n4 = (size_t)B_ * H_ / 4;
    size_t i = (size_t)blockIdx.x * blockDim.x + threadIdx.x;
    if (i >= n4) return;
    const size_t n = (size_t)B_ * H_;
    int j4 = (int)((i * 4) & (H_ - 1));

    float4 pz4 = ((const float4*)(g_pre + 0 * n))[i];
    float4 pi4 = ((const float4*)(g_pre + 1 * n))[i];
    float4 pf4 = ((const float4*)(g_pre + 2 * n))[i];
    float4 po4 = ((const float4*)(g_pre + 3 * n))[i];
    float4 cp4 = ((const float4*)c_prev)[i];
    float4 bz4 = *(const float4*)(bz + j4), rz4 = *(const float4*)(rbz + j4);
    float4 bi4 = *(const float4*)(bi + j4), ri4 = *(const float4*)(rbi + j4);
    float4 bf4 = *(const float4*)(bf + j4), rf4 = *(const float4*)(rbf + j4);
    float4 bo4 = *(const float4*)(bo + j4), ro4 = *(const float4*)(rbo + j4);

    float h[4], cc[4];
    float pzv[4] = {pz4.x + bz4.x + rz4.x, pz4.y + bz4.y + rz4.y,
                    pz4.z + bz4.z + rz4.z, pz4.w + bz4.w + rz4.w};
    float piv[4] = {pi4.x + bi4.x + ri4.x, pi4.y + bi4.y + ri4.y,
                    pi4.z + bi4.z + ri4.z, pi4.w + bi4.w + ri4.w};
    float pfv[4] = {pf4.x + bf4.x + rf4.x, pf4.y + bf4.y + rf4.y,
                    pf4.z + bf4.z + rf4.z, pf4.w + bf4.w + rf4.w};
    float pov[4] = {po4.x + bo4.x + ro4.x, po4.y + bo4.y + ro4.y,
                    po4.z + bo4.z + ro4.z, po4.w + bo4.w + ro4.w};
    float cpv[4] = {cp4.x, cp4.y, cp4.z, cp4.w};
#pragma unroll
    for (int k = 0; k < 4; ++k) {
        float z  = tanhf(pzv[k]);
        float ig = 1.f / (1.f + expf(-piv[k]));
        float fg = 1.f / (1.f + expf(-pfv[k]));
        float og = 1.f / (1.f + expf(-pov[k]));
        cc[k] = fg * cpv[k] + ig * z;
        h[k]  = og * tanhf(cc[k]);
    }
    ((float4*)out_h)[i] = make_float4(h[0], h[1], h[2], h[3]);
    ((float4*)out_c)[i] = make_float4(cc[0], cc[1], cc[2], cc[3]);
}

// ---------------------------------------------------------------------------
// Launch
// ---------------------------------------------------------------------------
extern "C" void kernel_launch(void* const* d_in, const int* in_sizes, int n_in,
                              void* d_out, int out_size)
{
    const float* x      = (const float*)d_in[0];
    const float* h_prev = (const float*)d_in[1];
    const float* c_prev = (const float*)d_in[2];
    const float* ln_g   = (const float*)d_in[3];
    const float* ln_b   = (const float*)d_in[4];
    const float* conv_w = (const float*)d_in[5];
    const float* conv_b = (const float*)d_in[6];
    const float* Wz = (const float*)d_in[7],  *bz  = (const float*)d_in[8];
    const float* Wi = (const float*)d_in[9],  *bi  = (const float*)d_in[10];
    const float* Wf = (const float*)d_in[11], *bf  = (const float*)d_in[12];
    const float* Wo = (const float*)d_in[13], *bo  = (const float*)d_in[14];
    const float* Rz = (const float*)d_in[15], *rbz = (const float*)d_in[16];
    const float* Ri = (const float*)d_in[17], *rbi = (const float*)d_in[18];
    const float* Rf = (const float*)d_in[19], *rbf = (const float*)d_in[20];
    const float* Ro = (const float*)d_in[21], *rbo = (const float*)d_in[22];

    float* out = (float*)d_out;

    cudaFuncSetAttribute(gemm_mma_kernel,
                         cudaFuncAttributeMaxDynamicSharedMemorySize, SMEM_TOTAL_G);

    void* p;
    cudaGetSymbolAddress(&p, g_x16); __half* x16 = (__half*)p;
    cudaGetSymbolAddress(&p, g_h16); __half* h16 = (__half*)p;

    const size_t nelem = (size_t)B_ * H_;

    // launch 1: LN + conv + SiLU (-> g_c16)
    ln_conv_kernel<<<B_, 256>>>(x, ln_g, ln_b, conv_w, conv_b);

    // launch 2: convert x and h_prev to fp16
    int n4 = (int)(((size_t)B_ * D_) / 4);
    dim3 cgrid((n4 + 255) / 256, 2);
    cvt2_kernel<<<cgrid, 256>>>(x, h_prev, x16, h16, n4);

    // launch 3: transpose all 8 weight tensors (vectorized)
    dim3 tgrid(8, 8, 32);
    wtrans8_kernel<<<tgrid, 256>>>(Wz, Wi, Wf, Wo, Rz, Ri, Rf, Ro);

    // launch 4: all GEMMs
    dim3 ggrid(4, 16, 16);
    gemm_mma_kernel<<<ggrid, 256, SMEM_TOTAL_G>>>();

    // launch 5: gates + state update
    gates_kernel<<<(int)((nelem / 4 + 255) / 256), 256>>>(
        c_prev, bz, bi, bf, bo, rbz, rbi, rbf, rbo, out, out + nelem);
}

// round 10
// speedup vs baseline: 5.9425x; 1.1067x over previous
#include <cuda_runtime.h>
#include <cuda_fp16.h>
#include <math.h>
#include <stdint.h>

// Problem constants
#define B_    4096
#define D_    2048
#define H_    2048
#define NB_   4
#define BIN_  512
#define BOUT_ 512
#define EPS_  1e-5f

// ---------------------------------------------------------------------------
// Device scratch (allocation-free)
// ---------------------------------------------------------------------------
__device__ __half g_x16[(size_t)B_ * D_];     // x in fp16
__device__ __half g_c16[(size_t)B_ * D_];     // SiLU(conv(LN(x))) in fp16
__device__ __half g_h16[(size_t)B_ * H_];     // h_prev in fp16
// Transposed weights: [tensor 0..7][NB*512*512] fp16, row=n, col=k
__device__ __half g_wt16[8][(size_t)NB_ * 512 * 512];
__device__ float g_pre[4ull * B_ * H_];

// ---------------------------------------------------------------------------
// PTX helpers
// ---------------------------------------------------------------------------
__device__ __forceinline__ uint32_t smem_u32(const void* p) {
    uint32_t a;
    asm("{ .reg .u64 t; cvta.to.shared.u64 t, %1; cvt.u32.u64 %0, t; }"
        : "=r"(a) : "l"(p));
    return a;
}

__device__ __forceinline__ void cp_async16(uint32_t dst, const void* src) {
    asm volatile("cp.async.cg.shared.global [%0], [%1], 16;"
                 :: "r"(dst), "l"(src) : "memory");
}
#define CP_COMMIT() asm volatile("cp.async.commit_group;" ::: "memory")

__device__ __forceinline__ void ldsm4(uint32_t* r, uint32_t addr) {
    asm volatile("ldmatrix.sync.aligned.m8n8.x4.shared.b16 {%0,%1,%2,%3}, [%4];"
                 : "=r"(r[0]), "=r"(r[1]), "=r"(r[2]), "=r"(r[3]) : "r"(addr));
}

__device__ __forceinline__ void mma16816(float* d, const uint32_t* a, const uint32_t* b) {
    asm volatile(
        "mma.sync.aligned.m16n8k16.row.col.f32.f16.f16.f32 "
        "{%0,%1,%2,%3}, {%4,%5,%6,%7}, {%8,%9}, {%0,%1,%2,%3};"
        : "+f"(d[0]), "+f"(d[1]), "+f"(d[2]), "+f"(d[3])
        : "r"(a[0]), "r"(a[1]), "r"(a[2]), "r"(a[3]), "r"(b[0]), "r"(b[1]));
}

// swizzled 16B-chunk offset inside a (rows x 64B) tile
__device__ __forceinline__ uint32_t swz(int row, int c) {
    return (uint32_t)(row * 64 + ((c ^ ((row >> 1) & 3)) << 4));
}

// ---------------------------------------------------------------------------
// Kernel 1: LayerNorm + causal conv3 + SiLU; also emits x in fp16
// ---------------------------------------------------------------------------
__global__ __launch_bounds__(256) void ln_conv_kernel(
    const float* __restrict__ x,
    const float* __restrict__ ln_g,
    const float* __restrict__ ln_b,
    const float* __restrict__ conv_w,
    const float* __restrict__ conv_b)
{
    __shared__ float xn[D_];
    __shared__ float red[256];

    const int row = blockIdx.x;
    const int tid = threadIdx.x;
    const float* xr = x + (size_t)row * D_;
    size_t base = (size_t)row * D_;

    float v[8];
    float s = 0.f, ss = 0.f;
#pragma unroll
    for (int i = 0; i < 8; ++i) {
        float t = xr[tid + i * 256];
        v[i] = t; s += t; ss += t * t;
    }
    // emit x in fp16 while reductions settle
#pragma unroll
    for (int i = 0; i < 8; ++i)
        g_x16[base + tid + i * 256] = __float2half(v[i]);

    red[tid] = s; __syncthreads();
    for (int off = 128; off > 0; off >>= 1) {
        if (tid < off) red[tid] += red[tid + off];
        __syncthreads();
    }
    const float mean = red[0] * (1.0f / D_);
    __syncthreads();
    red[tid] = ss; __syncthreads();
    for (int off = 128; off > 0; off >>= 1) {
        if (tid < off) red[tid] += red[tid + off];
        __syncthreads();
    }
    const float var = red[0] * (1.0f / D_) - mean * mean;
    const float rstd = rsqrtf(var + EPS_);
    __syncthreads();

#pragma unroll
    for (int i = 0; i < 8; ++i) {
        int d = tid + i * 256;
        xn[d] = (v[i] - mean) * rstd * ln_g[d] + ln_b[d];
    }
    __syncthreads();

    const float w0 = conv_w[0], w1 = conv_w[1], w2 = conv_w[2], cb = conv_b[0];
#pragma unroll
    for (int i = 0; i < 8; ++i) {
        int d = tid + i * 256;
        float a0 = (d >= 2) ? xn[d - 2] : 0.f;
        float a1 = (d >= 1) ? xn[d - 1] : 0.f;
        float xc = w0 * a0 + w1 * a1 + w2 * xn[d] + cb;
        float sg = 1.f / (1.f + expf(-xc));
        g_c16[base + d] = __float2half(xc * sg);
    }
}

// ---------------------------------------------------------------------------
// Kernel 2: fp32 -> fp16 convert (h_prev)
// ---------------------------------------------------------------------------
__global__ __launch_bounds__(256) void cvt_kernel(
    const float* __restrict__ src, __half* __restrict__ dst, int n4)
{
    int i = blockIdx.x * blockDim.x + threadIdx.x;
    if (i >= n4) return;
    float4 v = ((const float4*)src)[i];
    __half h[4] = { __float2half(v.x), __float2half(v.y),
                    __float2half(v.z), __float2half(v.w) };
    ((uint2*)dst)[i] = *(uint2*)h;
}

// ---------------------------------------------------------------------------
// Kernel 3: weight transpose+cvt, 64x64 tiles, vectorized 16B stores.
// ---------------------------------------------------------------------------
__global__ __launch_bounds__(256) void wtrans8_kernel(
    const float* __restrict__ W0, const float* __restrict__ W1,
    const float* __restrict__ W2, const float* __restrict__ W3,
    const float* __restrict__ W4, const float* __restrict__ W5,
    const float* __restrict__ W6, const float* __restrict__ W7)
{
    __shared__ __half tr[64][72];   // row stride 144B (16B-aligned)
    const int n0 = blockIdx.x * 64, k0 = blockIdx.y * 64;
    const int tens = blockIdx.z >> 2, nb = blockIdx.z & 3;
    const float* Ws[8] = {W0, W1, W2, W3, W4, W5, W6, W7};
    const float* Wb = Ws[tens] + (size_t)nb * 512 * 512;
    __half* Th = g_wt16[tens] + (size_t)nb * 512 * 512;

    const int tid = threadIdx.x;
#pragma unroll
    for (int it = 0; it < 4; ++it) {
        int t = tid + it * 256;
        int k = t >> 4, nq = (t & 15) * 4;
        float4 v = *(const float4*)(Wb + (size_t)(k0 + k) * 512 + n0 + nq);
        tr[nq + 0][k] = __float2half(v.x);
        tr[nq + 1][k] = __float2half(v.y);
        tr[nq + 2][k] = __float2half(v.z);
        tr[nq + 3][k] = __float2half(v.w);
    }
    __syncthreads();
#pragma unroll
    for (int it = 0; it < 2; ++it) {
        int s = tid + it * 256;
        int n = s >> 3, ch = (s & 7) * 8;
        uint4 val = *(const uint4*)&tr[n][ch];
        *(uint4*)(Th + (size_t)(n0 + n) * 512 + k0 + ch) = val;
    }
}

// ---------------------------------------------------------------------------
// Kernel 4: mma.sync fp16 GEMM.  CTA tile M=128 N=128 K=1024 (W then R).
// grid: (4 ntile, 32 mtile, 16 = gate*4+nblk), 256 threads (8 warps, 32x64).
// 2 CTAs/SM (regs capped at 128). smem: 4 stages x (A 8K + B 8K) = 64KB.
// ---------------------------------------------------------------------------
#define STAGE_BYTES 16384
#define OFF_A 0
#define OFF_B 8192
#define SMEM_TOTAL_G (4 * STAGE_BYTES)

__global__ __launch_bounds__(256, 2) void gemm_mma_kernel()
{
    extern __shared__ __align__(128) char smem[];
    const uint32_t sbase = smem_u32(smem);
    const int tid = threadIdx.x;
    const int lane = tid & 31;
    const int wid = tid >> 5;
    const int wm = wid & 3;          // warp row (4) -> 32 rows each
    const int wn = wid >> 2;         // warp col (2) -> 64 cols each

    const int ntile = blockIdx.x, mtile = blockIdx.y;
    const int gate = blockIdx.z >> 2, nblk = blockIdx.z & 3;
    const int row0 = mtile * 128;
    const int n0 = ntile * 128;

    const __half* a16 = (gate == 0 || gate == 3) ? g_x16 : g_c16;
    const __half* bw = g_wt16[gate];
    const __half* br = g_wt16[4 + gate];

    float acc[2][8][4];   // mh (16-row), n8 (8-col), frag
#pragma unroll
    for (int i = 0; i < 2; ++i)
#pragma unroll
        for (int j = 0; j < 8; ++j)
#pragma unroll
            for (int k = 0; k < 4; ++k) acc[i][j][k] = 0.f;

    // ---- load one k-chunk (32 k) into stage buf ----
    auto load_chunk = [&](int c, int buf) {
        const __half *A, *Bw;
        int kc;
        if (c < 16) { A = a16;   Bw = bw; kc = c * 32; }
        else        { A = g_h16; Bw = br; kc = (c - 16) * 32; }
        const size_t aoff = (size_t)row0 * D_ + nblk * 512 + kc;
        const size_t boff = (size_t)nblk * (512 * 512) + (size_t)n0 * 512 + kc;
        const uint32_t sb = sbase + (uint32_t)buf * STAGE_BYTES;
        // A: 128 rows x 4 16B-chunks = 512; 2 per thread
#pragma unroll
        for (int i = 0; i < 2; ++i) {
            int q = tid + i * 256;
            int row = q >> 2, cc = q & 3;
            cp_async16(sb + OFF_A + swz(row, cc), A + aoff + (size_t)row * D_ + cc * 8);
        }
        // B: 128 rows x 4 chunks = 512; 2 per thread
#pragma unroll
        for (int i = 0; i < 2; ++i) {
            int q = tid + i * 256;
            int row = q >> 2, cc = q & 3;
            cp_async16(sb + OFF_B + swz(row, cc), Bw + boff + (size_t)row * 512 + cc * 8);
        }
    };

    const int g = lane >> 3, lr = lane & 7;

    load_chunk(0, 0); CP_COMMIT();
    load_chunk(1, 1); CP_COMMIT();
    load_chunk(2, 2); CP_COMMIT();

#pragma unroll 1
    for (int c = 0; c < 32; ++c) {
        if (c <= 29)      asm volatile("cp.async.wait_group 2;" ::: "memory");
        else if (c == 30) asm volatile("cp.async.wait_group 1;" ::: "memory");
        else              asm volatile("cp.async.wait_group 0;" ::: "memory");
        __syncthreads();
        if (c + 3 < 32) { load_chunk(c + 3, (c + 3) & 3); CP_COMMIT(); }

        const uint32_t sb = sbase + (uint32_t)(c & 3) * STAGE_BYTES;

#pragma unroll
        for (int ks = 0; ks < 2; ++ks) {
            uint32_t bf[4][4];
#pragma unroll
            for (int nq = 0; nq < 4; ++nq) {
                int nrow = wn * 64 + nq * 16 + (g >> 1) * 8 + lr;
                ldsm4(bf[nq], sb + OFF_B + swz(nrow, ks * 2 + (g & 1)));
            }
#pragma unroll
            for (int mh = 0; mh < 2; ++mh) {
                uint32_t af[4];
                int row = wm * 32 + mh * 16 + (g & 1) * 8 + lr;
                ldsm4(af, sb + OFF_A + swz(row, ks * 2 + (g >> 1)));
#pragma unroll
                for (int nq = 0; nq < 4; ++nq)
#pragma unroll
                    for (int sub = 0; sub < 2; ++sub)
                        mma16816(acc[mh][nq * 2 + sub], af, &bf[nq][sub * 2]);
            }
        }
    }

    // Epilogue: direct fp32 stores to g_pre
    float* outp = g_pre + (size_t)gate * B_ * H_;
    const int colb = nblk * 512 + n0 + wn * 64 + (lane & 3) * 2;
    const int rowb = row0 + wm * 32 + (lane >> 2);
#pragma unroll
    for (int mh = 0; mh < 2; ++mh)
#pragma unroll
        for (int n8 = 0; n8 < 8; ++n8) {
            int col = colb + n8 * 8;
            int r0 = rowb + mh * 16;
            float* p0 = outp + (size_t)r0 * H_ + col;
            float* p1 = outp + (size_t)(r0 + 8) * H_ + col;
            *(float2*)p0 = make_float2(acc[mh][n8][0], acc[mh][n8][1]);
            *(float2*)p1 = make_float2(acc[mh][n8][2], acc[mh][n8][3]);
        }
}

// ---------------------------------------------------------------------------
// Kernel 5: gates + state update (float4 vectorized)
// ---------------------------------------------------------------------------
__global__ __launch_bounds__(256) void gates_kernel(
    const float* __restrict__ c_prev,
    const float* __restrict__ bz, const float* __restrict__ bi,
    const float* __restrict__ bf, const float* __restrict__ bo,
    const float* __restrict__ rbz, const float* __restrict__ rbi,
    const float* __restrict__ rbf, const float* __restrict__ rbo,
    float* __restrict__ out_h, float* __restrict__ out_c)
{
    const size_t n4 = (size_t)B_ * H_ / 4;
    size_t i = (size_t)blockIdx.x * blockDim.x + threadIdx.x;
    if (i >= n4) return;
    const size_t n = (size_t)B_ * H_;
    int j4 = (int)((i * 4) & (H_ - 1));

    float4 pz4 = ((const float4*)(g_pre + 0 * n))[i];
    float4 pi4 = ((const float4*)(g_pre + 1 * n))[i];
    float4 pf4 = ((const float4*)(g_pre + 2 * n))[i];
    float4 po4 = ((const float4*)(g_pre + 3 * n))[i];
    float4 cp4 = ((const float4*)c_prev)[i];
    float4 bz4 = *(const float4*)(bz + j4), rz4 = *(const float4*)(rbz + j4);
    float4 bi4 = *(const float4*)(bi + j4), ri4 = *(const float4*)(rbi + j4);
    float4 bf4 = *(const float4*)(bf + j4), rf4 = *(const float4*)(rbf + j4);
    float4 bo4 = *(const float4*)(bo + j4), ro4 = *(const float4*)(rbo + j4);

    float h[4], cc[4];
    float pzv[4] = {pz4.x + bz4.x + rz4.x, pz4.y + bz4.y + rz4.y,
                    pz4.z + bz4.z + rz4.z, pz4.w + bz4.w + rz4.w};
    float piv[4] = {pi4.x + bi4.x + ri4.x, pi4.y + bi4.y + ri4.y,
                    pi4.z + bi4.z + ri4.z, pi4.w + bi4.w + ri4.w};
    float pfv[4] = {pf4.x + bf4.x + rf4.x, pf4.y + bf4.y + rf4.y,
                    pf4.z + bf4.z + rf4.z, pf4.w + bf4.w + rf4.w};
    float pov[4] = {po4.x + bo4.x + ro4.x, po4.y + bo4.y + ro4.y,
                    po4.z + bo4.z + ro4.z, po4.w + bo4.w + ro4.w};
    float cpv[4] = {cp4.x, cp4.y, cp4.z, cp4.w};
#pragma unroll
    for (int k = 0; k < 4; ++k) {
        float z  = tanhf(pzv[k]);
        float ig = 1.f / (1.f + expf(-piv[k]));
        float fg = 1.f / (1.f + expf(-pfv[k]));
        float og = 1.f / (1.f + expf(-pov[k]));
        cc[k] = fg * cpv[k] + ig * z;
        h[k]  = og * tanhf(cc[k]);
    }
    ((float4*)out_h)[i] = make_float4(h[0], h[1], h[2], h[3]);
    ((float4*)out_c)[i] = make_float4(cc[0], cc[1], cc[2], cc[3]);
}

// ---------------------------------------------------------------------------
// Launch
// ---------------------------------------------------------------------------
extern "C" void kernel_launch(void* const* d_in, const int* in_sizes, int n_in,
                              void* d_out, int out_size)
{
    const float* x      = (const float*)d_in[0];
    const float* h_prev = (const float*)d_in[1];
    const float* c_prev = (const float*)d_in[2];
    const float* ln_g   = (const float*)d_in[3];
    const float* ln_b   = (const float*)d_in[4];
    const float* conv_w = (const float*)d_in[5];
    const float* conv_b = (const float*)d_in[6];
    const float* Wz = (const float*)d_in[7],  *bz  = (const float*)d_in[8];
    const float* Wi = (const float*)d_in[9],  *bi  = (const float*)d_in[10];
    const float* Wf = (const float*)d_in[11], *bf  = (const float*)d_in[12];
    const float* Wo = (const float*)d_in[13], *bo  = (const float*)d_in[14];
    const float* Rz = (const float*)d_in[15], *rbz = (const float*)d_in[16];
    const float* Ri = (const float*)d_in[17], *rbi = (const float*)d_in[18];
    const float* Rf = (const float*)d_in[19], *rbf = (const float*)d_in[20];
    const float* Ro = (const float*)d_in[21], *rbo = (const float*)d_in[22];

    float* out = (float*)d_out;

    cudaFuncSetAttribute(gemm_mma_kernel,
                         cudaFuncAttributeMaxDynamicSharedMemorySize, SMEM_TOTAL_G);

    void* p;
    cudaGetSymbolAddress(&p, g_h16); __half* h16 = (__half*)p;

    const size_t nelem = (size_t)B_ * H_;

    // launch 1: LN + conv + SiLU (-> g_c16) + x cvt (-> g_x16)
    ln_conv_kernel<<<B_, 256>>>(x, ln_g, ln_b, conv_w, conv_b);

    // launch 2: convert h_prev to fp16
    int n4 = (int)(((size_t)B_ * D_) / 4);
    cvt_kernel<<<(n4 + 255) / 256, 256>>>(h_prev, h16, n4);

    // launch 3: transpose all 8 weight tensors (vectorized)
    dim3 tgrid(8, 8, 32);
    wtrans8_kernel<<<tgrid, 256>>>(Wz, Wi, Wf, Wo, Rz, Ri, Rf, Ro);

    // launch 4: all GEMMs
    dim3 ggrid(4, 32, 16);
    gemm_mma_kernel<<<ggrid, 256, SMEM_TOTAL_G>>>();

    // launch 5: gates + state update
    gates_kernel<<<(int)((nelem / 4 + 255) / 256), 256>>>(
        c_prev, bz, bi, bf, bo, rbz, rbi, rbf, rbo, out, out + nelem);
}